// round 5
// baseline (speedup 1.0000x reference)
#include <cuda_runtime.h>
#include <cuda_bf16.h>
#include <cstddef>

#define DD 256
#define HH 8
#define LL 64
#define HL 512
#define NEURONS 4096
#define TBINS 1024
#define VBUCK 256
#define NBATCH 16
#define EVSTRIDE 13600
#define MAXE 200704
#define NSPLIT 18
#define NROWS 5376

// ---------------- static device scratch ----------------
__device__ __align__(16) float g_embcat[NROWS * DD];
__device__ float g_rowmean[NROWS];
__device__ float g_rowmsq[NROWS];
__device__ __align__(16) float g_xl[LL * DD];
__device__ __align__(16) float g_qh[HL * 32];
__device__ float g_colsum[512];
__device__ float g_colV[256];
__device__ float g_qcK[HL];
__device__ __align__(16) float g_Wc[DD * 768];
__device__ __align__(16) float g_T[NROWS * 768];
__device__ float g_me[MAXE];
__device__ float g_re[MAXE];
__device__ int   g_cnt[NBATCH];
__device__ int   g_chunkcnt[256 * NBATCH];
__device__ int   g_chunkbase[256 * NBATCH];
__device__ int   g_evlist[NBATCH * EVSTRIDE];
__device__ float g_psum[NBATCH * NSPLIT * HL];
__device__ float g_pacc[NBATCH * NSPLIT * 32 * HL];
__device__ __align__(16) float g_attv[NBATCH * LL * DD];
__device__ __align__(16) float g_lat [NBATCH * LL * DD];
__device__ __align__(16) float g_x   [NBATCH * LL * DD];
__device__ __align__(16) float g_h   [NBATCH * LL * 1024];
__device__ __align__(16) float g_qkv [NBATCH * LL * 768];
__device__ __align__(16) float g_obuf[NBATCH * LL * DD];
__device__ __align__(16) float g_kvb [NBATCH * LL * 512];
__device__ __align__(16) float g_qb  [2 * DD];

__device__ __forceinline__ float gelu_f(float x) {
    float x3 = x * x * x;
    float u = 0.7978845608028654f * (x + 0.044715f * x3);
    return 0.5f * x * (1.0f + tanhf(u));
}

// ---------------- prep kernels ----------------
__global__ void k_copy_emb(const float* __restrict__ ne, const float* __restrict__ te,
                           const float* __restrict__ ve) {
    size_t i = (size_t)blockIdx.x * 256 + threadIdx.x;
    float v;
    if (i < (size_t)NEURONS * DD)                 v = ne[i];
    else if (i < (size_t)(NEURONS + TBINS) * DD)  v = te[i - (size_t)NEURONS * DD];
    else                                          v = ve[i - (size_t)(NEURONS + TBINS) * DD];
    g_embcat[i] = v;
}

__global__ void k_rowstats() {
    __shared__ float red[16];
    int r = blockIdx.x, t = threadIdx.x;
    float x = g_embcat[(size_t)r * DD + t];
    float s = x, q = x * x;
#pragma unroll
    for (int o = 16; o > 0; o >>= 1) { s += __shfl_xor_sync(~0u, s, o); q += __shfl_xor_sync(~0u, q, o); }
    if ((t & 31) == 0) { red[t >> 5] = s; red[8 + (t >> 5)] = q; }
    __syncthreads();
    if (t == 0) {
        float ss = 0, qq = 0;
        for (int i = 0; i < 8; i++) { ss += red[i]; qq += red[8 + i]; }
        g_rowmean[r] = ss * (1.0f / DD);
        g_rowmsq[r]  = qq * (1.0f / DD);
    }
}

__global__ void k_ln(const float* __restrict__ in, float* __restrict__ out,
                     const float* __restrict__ w, const float* __restrict__ b) {
    __shared__ float red[16];
    int r = blockIdx.x, t = threadIdx.x;
    float x = in[(size_t)r * DD + t];
    float s = x, q = x * x;
#pragma unroll
    for (int o = 16; o > 0; o >>= 1) { s += __shfl_xor_sync(~0u, s, o); q += __shfl_xor_sync(~0u, q, o); }
    if ((t & 31) == 0) { red[t >> 5] = s; red[8 + (t >> 5)] = q; }
    __syncthreads();
    if (t == 0) {
        float ss = 0, qq = 0;
        for (int i = 0; i < 8; i++) { ss += red[i]; qq += red[8 + i]; }
        red[0] = ss; red[8] = qq;
    }
    __syncthreads();
    float mean = red[0] * (1.0f / DD);
    float var  = red[8] * (1.0f / DD) - mean * mean;
    float rstd = rsqrtf(var + 1e-5f);
    float y = (x - mean) * rstd;
    if (w) y = fmaf(y, w[t], b[t]);
    out[(size_t)r * DD + t] = y;
}

// q~[hl][i] = (ln(lat_init)[l] @ Wq_c)[h*32+i] * 32^-0.5,  hl = h*64+l
__global__ void k_q(const float* __restrict__ Wq) {
    __shared__ float xr[DD];
    int l = blockIdx.x, c = threadIdx.x;
    xr[c] = g_xl[l * DD + c];
    __syncthreads();
    float a = 0;
#pragma unroll 8
    for (int d = 0; d < DD; d++) a = fmaf(xr[d], Wq[d * DD + c], a);
    int h = c >> 5, i = c & 31;
    g_qh[((h << 6) + l) * 32 + i] = a * 0.17677669529663687f;
}

__global__ void k_colsum(const float* __restrict__ Wkv) {
    int j = blockIdx.x * 256 + threadIdx.x;
    float s = 0;
    for (int d = 0; d < DD; d++) s += Wkv[(size_t)d * 512 + j];
    g_colsum[j] = s;
    if (j >= 256) g_colV[j - 256] = s;
}

__global__ void k_qc() {
    int hl = threadIdx.x;
    int h = hl >> 6;
    float a = 0;
#pragma unroll
    for (int i = 0; i < 32; i++) a = fmaf(g_qh[hl * 32 + i], g_colsum[h * 32 + i], a);
    g_qcK[hl] = a;
}

// Wc[:, :512] = A (score projection folded with q),  Wc[:, 512:768] = Wkv V-part
__global__ void k_buildWc(const float* __restrict__ Wkv) {
    __shared__ float wr[256];
    int d = blockIdx.x, c = threadIdx.x;
    if (c < 256) wr[c] = Wkv[(size_t)d * 512 + c];
    __syncthreads();
    float out;
    if (c < 512) {
        int h = c >> 6;
        float a = 0;
#pragma unroll
        for (int i = 0; i < 32; i++) a = fmaf(wr[h * 32 + i], g_qh[c * 32 + i], a);
        out = a;
    } else {
        out = Wkv[(size_t)d * 512 + 256 + (c - 512)];
    }
    g_Wc[(size_t)d * 768 + c] = out;
}

// ---------------- generic fp32 GEMM, 128x128 tile, 8x8/thread ----------------
// flags: 1 = gelu epilogue, 2 = accumulate into C
__global__ void __launch_bounds__(256) k_gemm(const float* __restrict__ A, const float* __restrict__ W,
                                              float* __restrict__ C, int R, int K, int N, int flags) {
    __shared__ float As[16][132];
    __shared__ float Ws[16][132];
    int t = threadIdx.x;
    int rbase = blockIdx.x * 128, nbase = blockIdx.y * 128;
    int tr = t >> 4, tc = t & 15;
    float acc[8][8];
#pragma unroll
    for (int x = 0; x < 8; x++)
#pragma unroll
        for (int y = 0; y < 8; y++) acc[x][y] = 0.f;

    for (int k0 = 0; k0 < K; k0 += 16) {
#pragma unroll
        for (int j = 0; j < 2; j++) {
            int q = t * 2 + j;
            int m = q >> 2, k4 = (q & 3) * 4;
            int r = rbase + m;
            float4 av = make_float4(0.f, 0.f, 0.f, 0.f);
            if (r < R) av = *(const float4*)(A + (size_t)r * K + k0 + k4);
            As[k4 + 0][m] = av.x; As[k4 + 1][m] = av.y;
            As[k4 + 2][m] = av.z; As[k4 + 3][m] = av.w;
            int n4 = (q & 31) * 4, kw = q >> 5;
            float4 wv = *(const float4*)(W + (size_t)(k0 + kw) * N + nbase + n4);
            *(float4*)&Ws[kw][n4] = wv;
        }
        __syncthreads();
#pragma unroll
        for (int kk = 0; kk < 16; kk++) {
            float a[8], w[8];
#pragma unroll
            for (int x = 0; x < 8; x++) a[x] = As[kk][tr * 8 + x];
#pragma unroll
            for (int y = 0; y < 8; y++) w[y] = Ws[kk][tc * 8 + y];
#pragma unroll
            for (int x = 0; x < 8; x++)
#pragma unroll
                for (int y = 0; y < 8; y++) acc[x][y] = fmaf(a[x], w[y], acc[x][y]);
        }
        __syncthreads();
    }
#pragma unroll
    for (int x = 0; x < 8; x++) {
        int r = rbase + tr * 8 + x;
        if (r >= R) break;
        float* crow = C + (size_t)r * N + nbase + tc * 8;
#pragma unroll
        for (int y = 0; y < 8; y++) {
            float v = acc[x][y];
            if (flags & 1) v = gelu_f(v);
            if (flags & 2) crow[y] += v; else crow[y] = v;
        }
    }
}

// ---------------- deterministic event grouping (counting sort) ----------------
__global__ void k_count(const int* __restrict__ bix, int E) {
    __shared__ int sc[NBATCH];
    int c = blockIdx.x;
    if (threadIdx.x < NBATCH) sc[threadIdx.x] = 0;
    __syncthreads();
    int base = c << 10;
    for (int i = threadIdx.x; i < 1024; i += blockDim.x) {
        int e = base + i;
        if (e < E) atomicAdd(&sc[bix[e]], 1);
    }
    __syncthreads();
    if (threadIdx.x < NBATCH) g_chunkcnt[c * NBATCH + threadIdx.x] = sc[threadIdx.x];
}

__global__ void k_scan(int nch) {
    int b = threadIdx.x;
    if (b < NBATCH) {
        int run = 0;
        for (int c = 0; c < nch; c++) {
            int v = g_chunkcnt[c * NBATCH + b];
            g_chunkbase[c * NBATCH + b] = run;
            run += v;
        }
        g_cnt[b] = run;
    }
}

__global__ void k_scatter(const int* __restrict__ bix, int E) {
    __shared__ int loc[48];
    int c = blockIdx.x, lane = threadIdx.x;
    if (lane < NBATCH) loc[lane] = g_chunkbase[c * NBATCH + lane];
    loc[16 + lane] = 0;
    __syncwarp();
    int base = c << 10;
    for (int i = 0; i < 32; i++) {
        int e = base + i * 32 + lane;
        bool valid = e < E;
        int b_ = 0;
        if (valid) b_ = bix[e];
        int bb = valid ? b_ : 16 + lane;
        unsigned mm = __match_any_sync(0xffffffffu, bb);
        int rank = __popc(mm & ((1u << lane) - 1u));
        int leader = __ffs(mm) - 1;
        int start = 0;
        if (lane == leader) { start = loc[bb]; loc[bb] = start + __popc(mm); }
        start = __shfl_sync(0xffffffffu, start, leader);
        if (valid) g_evlist[b_ * EVSTRIDE + start + rank] = e;
        __syncwarp();
    }
}

// ---------------- per-event LN stats ----------------
__global__ void k_stats(const int* __restrict__ nid, const int* __restrict__ tb,
                        const int* __restrict__ vl, int E) {
    int e = blockIdx.x * 8 + (threadIdx.x >> 5);
    int lane = threadIdx.x & 31;
    if (e >= E) return;
    int n = nid[e], t = tb[e], v = vl[e];
    const float* rn = g_embcat + (size_t)n * DD;
    const float* rt = g_embcat + (size_t)(NEURONS + t) * DD;
    const float* rv = g_embcat + (size_t)(NEURONS + TBINS + v) * DD;
    float dnt = 0, dnv = 0, dtv = 0;
    for (int d = lane; d < DD; d += 32) {
        float a = rn[d], b = rt[d], cc = rv[d];
        dnt = fmaf(a, b, dnt); dnv = fmaf(a, cc, dnv); dtv = fmaf(b, cc, dtv);
    }
#pragma unroll
    for (int o = 16; o > 0; o >>= 1) {
        dnt += __shfl_xor_sync(~0u, dnt, o);
        dnv += __shfl_xor_sync(~0u, dnv, o);
        dtv += __shfl_xor_sync(~0u, dtv, o);
    }
    if (lane == 0) {
        float m = g_rowmean[n] + g_rowmean[NEURONS + t] + g_rowmean[NEURONS + TBINS + v];
        float msq = g_rowmsq[n] + g_rowmsq[NEURONS + t] + g_rowmsq[NEURONS + TBINS + v]
                  + (dnt + dnv + dtv) * (2.0f / DD);
        float var = msq - m * m;
        g_me[e] = m;
        g_re[e] = rsqrtf(var + 1e-5f);
    }
}

// ---------------- fused ragged cross-attention ----------------
__global__ void __launch_bounds__(512, 2) k_cross(const int* __restrict__ nid,
                                                  const int* __restrict__ tb,
                                                  const int* __restrict__ vl) {
    int bs = blockIdx.x;
    int b = bs / NSPLIT, sp = bs - b * NSPLIT;
    int t = threadIdx.x;
    int cnt = g_cnt[b];
    if (cnt > EVSTRIDE) cnt = EVSTRIDE;
    int e0 = (int)((long long)cnt * sp / NSPLIT);
    int e1 = (int)((long long)cnt * (sp + 1) / NSPLIT);

    __shared__ float sv[8][256];
    float qc = g_qcK[t];
    float cv = (t < 256) ? g_colV[t] : 0.f;
    float acc[32];
#pragma unroll
    for (int i = 0; i < 32; i++) acc[i] = 0.f;
    float sumP = 0.f;
    int h32 = (t >> 6) << 5;
    const int* evl = g_evlist + b * EVSTRIDE;

    for (int base = e0; base < e1; base += 8) {
        int nb = min(8, e1 - base);
        float p[8];
        for (int j = 0; j < nb; j++) {
            int e = evl[base + j];
            int n = nid[e], tt = tb[e], vv = vl[e];
            float m = g_me[e], r = g_re[e];
            const float* Tn = g_T + (size_t)n * 768;
            const float* Tt = g_T + (size_t)(NEURONS + tt) * 768;
            const float* Tv = g_T + (size_t)(NEURONS + TBINS + vv) * 768;
            float s = r * (Tn[t] + Tt[t] + Tv[t]) - (r * m) * qc;
            p[j] = __expf(s);
            sumP += p[j];
            if (t < 256) sv[j][t] = r * (Tn[512 + t] + Tt[512 + t] + Tv[512 + t]) - (r * m) * cv;
        }
        __syncthreads();
        for (int j = 0; j < nb; j++) {
            float pj = p[j];
            const float4* vp = (const float4*)(sv[j] + h32);
#pragma unroll
            for (int i = 0; i < 8; i++) {
                float4 v4 = vp[i];
                acc[4 * i + 0] = fmaf(pj, v4.x, acc[4 * i + 0]);
                acc[4 * i + 1] = fmaf(pj, v4.y, acc[4 * i + 1]);
                acc[4 * i + 2] = fmaf(pj, v4.z, acc[4 * i + 2]);
                acc[4 * i + 3] = fmaf(pj, v4.w, acc[4 * i + 3]);
            }
        }
        __syncthreads();
    }
    g_psum[(size_t)bs * HL + t] = sumP;
    float* pa = g_pacc + (size_t)bs * 32 * HL;
#pragma unroll
    for (int i = 0; i < 32; i++) pa[i * HL + t] = acc[i];
}

__global__ void k_reduce() {
    int b = blockIdx.x, hl = threadIdx.x;
    float tot = 0;
    for (int s = 0; s < NSPLIT; s++) tot += g_psum[(size_t)(b * NSPLIT + s) * HL + hl];
    float inv = (tot > 0.f) ? 1.0f / tot : 0.f;
    float o[32];
#pragma unroll
    for (int i = 0; i < 32; i++) o[i] = 0.f;
    for (int s = 0; s < NSPLIT; s++) {
        const float* base = g_pacc + (size_t)(b * NSPLIT + s) * 32 * HL;
#pragma unroll
        for (int i = 0; i < 32; i++) o[i] += base[i * HL + hl];
    }
    int h = hl >> 6, l = hl & 63;
    float* dst = g_attv + ((size_t)(b * LL + l)) * DD + h * 32;
#pragma unroll
    for (int i = 0; i < 32; i++) dst[i] = o[i] * inv;
}

__global__ void k_prefill(const float* __restrict__ lat0) {
    int row = blockIdx.x, t = threadIdx.x;
    g_lat[(size_t)row * DD + t] = lat0[(row & 63) * DD + t];
}

// ---------------- latent self-attention (per (b,h)) ----------------
__global__ void k_selfattn(const float* __restrict__ qkv, float* __restrict__ obuf) {
    int b = blockIdx.x >> 3, h = blockIdx.x & 7;
    __shared__ float qs[64][33], ks[64][33], vs[64][33], ps[64][65];
    int t = threadIdx.x;
    for (int id = t; id < 64 * 32; id += 256) {
        int l = id >> 5, i = id & 31;
        const float* base = qkv + ((size_t)(b * LL + l)) * 768 + h * 32 + i;
        qs[l][i] = base[0];
        ks[l][i] = base[256];
        vs[l][i] = base[512];
    }
    __syncthreads();
    int ql = t >> 2, k0 = (t & 3) * 16;
    for (int kk = 0; kk < 16; kk++) {
        int k = k0 + kk;
        float s = 0;
#pragma unroll
        for (int d = 0; d < 32; d++) s = fmaf(qs[ql][d], ks[k][d], s);
        ps[ql][k] = s * 0.17677669529663687f;
    }
    __syncthreads();
    if (t < 64) {
        float mx = -1e30f;
        for (int k = 0; k < 64; k++) mx = fmaxf(mx, ps[t][k]);
        float sum = 0;
        for (int k = 0; k < 64; k++) { float p = __expf(ps[t][k] - mx); ps[t][k] = p; sum += p; }
        float inv = 1.0f / sum;
        for (int k = 0; k < 64; k++) ps[t][k] *= inv;
    }
    __syncthreads();
    int i = t & 31, l0 = t >> 5;
    for (int j = 0; j < 8; j++) {
        int l = l0 + j * 8;
        float o = 0;
        for (int k = 0; k < 64; k++) o = fmaf(ps[l][k], vs[k][i], o);
        obuf[((size_t)(b * LL + l)) * DD + h * 32 + i] = o;
    }
}

// ---------------- behavior decoder + logits ----------------
__global__ void k_behav(const float* __restrict__ bh_wo, float* __restrict__ out) {
    int b = blockIdx.x, t = threadIdx.x;
    __shared__ float sc[16][65];
    __shared__ float ov[2][256];
    __shared__ float red[8];
    for (int id = t; id < 1024; id += 256) {
        int jh = id >> 6, k = id & 63;
        int j = jh >> 3, h = jh & 7;
        const float* kr = g_kvb + ((size_t)(b * LL + k)) * 512 + h * 32;
        const float* qr = g_qb + j * DD + h * 32;
        float s = 0;
#pragma unroll
        for (int d = 0; d < 32; d++) s = fmaf(qr[d], kr[d], s);
        sc[jh][k] = s * 0.17677669529663687f;
    }
    __syncthreads();
    if (t < 16) {
        float mx = -1e30f;
        for (int k = 0; k < 64; k++) mx = fmaxf(mx, sc[t][k]);
        float sum = 0;
        for (int k = 0; k < 64; k++) { float p = __expf(sc[t][k] - mx); sc[t][k] = p; sum += p; }
        float inv = 1.0f / sum;
        for (int k = 0; k < 64; k++) sc[t][k] *= inv;
    }
    __syncthreads();
    for (int id = t; id < 512; id += 256) {
        int j = id >> 8, c = id & 255, h = c >> 5;
        float o = 0;
        for (int k = 0; k < 64; k++)
            o = fmaf(sc[j * 8 + h][k], g_kvb[((size_t)(b * LL + k)) * 512 + 256 + c], o);
        ov[j][c] = o;
    }
    __syncthreads();
    for (int j = 0; j < 2; j++) {
        float v = ov[j][t] * bh_wo[t];
#pragma unroll
        for (int o = 16; o > 0; o >>= 1) v += __shfl_xor_sync(~0u, v, o);
        if ((t & 31) == 0) red[t >> 5] = v;
        __syncthreads();
        if (t == 0) {
            float s = 0;
            for (int w = 0; w < 8; w++) s += red[w];
            out[b * 2 + j] = s;
        }
        __syncthreads();
    }
}

__global__ void k_logits(const float* __restrict__ sp_w, const float* __restrict__ sp_b,
                         float* __restrict__ out) {
    int b = blockIdx.x, t = threadIdx.x;
    __shared__ float mean[DD];
    float s = 0;
    for (int l = 0; l < LL; l++) s += g_lat[((size_t)(b * LL + l)) * DD + t];
    mean[t] = s * (1.0f / LL);
    __syncthreads();
    if (t < 64) {
        float a = sp_b[t];
        for (int d = 0; d < DD; d++) a = fmaf(mean[d], sp_w[d * 64 + t], a);
        out[32 + b * 64 + t] = a;
    }
}

// ---------------- host driver ----------------
extern "C" void kernel_launch(void* const* d_in, const int* in_sizes, int n_in,
                              void* d_out, int out_size) {
    const float* W[21];
    int wi = 0;
    const int* ids[4] = {nullptr, nullptr, nullptr, nullptr};
    int E = 0;
    for (int i = 0; i < n_in; i++) {
        int s = in_sizes[i];
        if (s <= 2) continue;
        if (!E && s >= 50000 && i + 3 < n_in && in_sizes[i + 1] == s &&
            in_sizes[i + 2] == s && in_sizes[i + 3] == s) {
            for (int j = 0; j < 4; j++) ids[j] = (const int*)d_in[i + j];
            E = s;
            i += 3;
            continue;
        }
        if (wi < 21) W[wi++] = (const float*)d_in[i];
    }
    const float *ne = W[0], *te = W[1], *ve = W[2], *lat0 = W[3], *Wq = W[4], *Wkv = W[5],
                *Wo = W[6], *W1 = W[7], *W2 = W[8], *Wqkv_s = W[9], *Wo_s = W[10],
                *W1_s = W[11], *W2_s = W[12], *bhq = W[13], *bhwq = W[14], *bhwkv = W[15],
                *bhwo = W[16], *lnw = W[17], *lnb = W[18], *spw = W[19], *spb = W[20];
    const int *nid = ids[0], *tbv = ids[1], *vlv = ids[2], *bix = ids[3];
    float* out = (float*)d_out;

    float *p_embcat, *p_Wc, *p_T, *p_xl, *p_x, *p_h, *p_lat, *p_qkv, *p_obuf, *p_kvb, *p_qb, *p_attv;
    cudaGetSymbolAddress((void**)&p_embcat, g_embcat);
    cudaGetSymbolAddress((void**)&p_Wc, g_Wc);
    cudaGetSymbolAddress((void**)&p_T, g_T);
    cudaGetSymbolAddress((void**)&p_xl, g_xl);
    cudaGetSymbolAddress((void**)&p_x, g_x);
    cudaGetSymbolAddress((void**)&p_h, g_h);
    cudaGetSymbolAddress((void**)&p_lat, g_lat);
    cudaGetSymbolAddress((void**)&p_qkv, g_qkv);
    cudaGetSymbolAddress((void**)&p_obuf, g_obuf);
    cudaGetSymbolAddress((void**)&p_kvb, g_kvb);
    cudaGetSymbolAddress((void**)&p_qb, g_qb);
    cudaGetSymbolAddress((void**)&p_attv, g_attv);

    int nch = (E + 1023) >> 10;

    // --- precompute tables ---
    k_copy_emb<<<NROWS, 256>>>(ne, te, ve);
    k_rowstats<<<NROWS, 256>>>();
    k_ln<<<64, 256>>>(lat0, p_xl, nullptr, nullptr);
    k_q<<<64, 256>>>(Wq);
    k_colsum<<<2, 256>>>(Wkv);
    k_qc<<<1, 512>>>();
    k_buildWc<<<256, 768>>>(Wkv);
    {
        dim3 g(42, 6);
        k_gemm<<<g, 256>>>(p_embcat, p_Wc, p_T, NROWS, 256, 768, 0);
    }

    // --- event grouping + stats ---
    k_count<<<nch, 256>>>(bix, E);
    k_scan<<<1, 16>>>(nch);
    k_scatter<<<nch, 32>>>(bix, E);
    k_stats<<<(E + 7) / 8, 256>>>(nid, tbv, vlv, E);

    // --- fused cross attention ---
    k_cross<<<NBATCH * NSPLIT, 512>>>(nid, tbv, vlv);
    k_reduce<<<NBATCH, 512>>>();

    // --- latent pipeline ---
    k_prefill<<<NBATCH * LL, 256>>>(lat0);
    { dim3 g(8, 2); k_gemm<<<g, 256>>>(p_attv, Wo, p_lat, 1024, 256, 256, 2); }
    k_ln<<<1024, 256>>>(p_lat, p_x, nullptr, nullptr);
    { dim3 g(8, 8); k_gemm<<<g, 256>>>(p_x, W1, p_h, 1024, 256, 1024, 1); }
    { dim3 g(8, 2); k_gemm<<<g, 256>>>(p_h, W2, p_lat, 1024, 1024, 256, 2); }

    for (int i = 0; i < 2; i++) {
        k_ln<<<1024, 256>>>(p_lat, p_x, nullptr, nullptr);
        { dim3 g(8, 6); k_gemm<<<g, 256>>>(p_x, Wqkv_s + (size_t)i * 256 * 768, p_qkv, 1024, 256, 768, 0); }
        k_selfattn<<<NBATCH * 8, 256>>>(p_qkv, p_obuf);
        { dim3 g(8, 2); k_gemm<<<g, 256>>>(p_obuf, Wo_s + (size_t)i * 256 * 256, p_lat, 1024, 256, 256, 2); }
        k_ln<<<1024, 256>>>(p_lat, p_x, nullptr, nullptr);
        { dim3 g(8, 8); k_gemm<<<g, 256>>>(p_x, W1_s + (size_t)i * 256 * 1024, p_h, 1024, 256, 1024, 1); }
        { dim3 g(8, 2); k_gemm<<<g, 256>>>(p_h, W2_s + (size_t)i * 1024 * 256, p_lat, 1024, 1024, 256, 2); }
    }

    // --- behavior decoder ---
    k_ln<<<1024, 256>>>(p_lat, p_x, lnw, lnb);
    { dim3 g(8, 4); k_gemm<<<g, 256>>>(p_x, bhwkv, p_kvb, 1024, 256, 512, 0); }
    { dim3 g(1, 2); k_gemm<<<g, 256>>>(bhq, bhwq, p_qb, 2, 256, 256, 0); }
    k_behav<<<NBATCH, 256>>>(bhwo, out);

    // --- spike logits ---
    k_logits<<<NBATCH, 256>>>(spw, spb, out);
}

// round 6
// speedup vs baseline: 1.2572x; 1.2572x over previous
#include <cuda_runtime.h>
#include <cuda_bf16.h>
#include <cstddef>

#define DD 256
#define HH 8
#define LL 64
#define HL 512
#define NEURONS 4096
#define TBINS 1024
#define VBUCK 256
#define NBATCH 16
#define EVSTRIDE 13600
#define MAXE 200704
#define NSPLIT 9
#define NROWS 5376

// ---------------- static device scratch ----------------
__device__ __align__(16) float g_embcat[NROWS * DD];
__device__ float g_rowmean[NROWS];
__device__ float g_rowmsq[NROWS];
__device__ __align__(16) float g_xl[LL * DD];
__device__ __align__(16) float g_qh[HL * 32];
__device__ float g_colsum[512];
__device__ float g_colV[256];
__device__ float g_qcK[HL];
__device__ __align__(16) float g_Wc[DD * 768];
__device__ __align__(16) __nv_bfloat16 g_Ts[NROWS * 512];   // bf16 score table
__device__ __align__(16) float g_Tv[NROWS * 256];           // fp32 V table
__device__ float g_me[MAXE];
__device__ float g_re[MAXE];
__device__ int   g_cnt[NBATCH];
__device__ int   g_chunkcnt[256 * NBATCH];
__device__ int   g_chunkbase[256 * NBATCH];
__device__ int   g_evlist[NBATCH * EVSTRIDE];
__device__ float g_psum[NBATCH * NSPLIT * HL];
__device__ float g_pacc[NBATCH * NSPLIT * 32 * HL];
__device__ __align__(16) float g_attv[NBATCH * LL * DD];
__device__ __align__(16) float g_lat [NBATCH * LL * DD];
__device__ __align__(16) float g_x   [NBATCH * LL * DD];
__device__ __align__(16) float g_h   [NBATCH * LL * 1024];
__device__ __align__(16) float g_qkv [NBATCH * LL * 768];
__device__ __align__(16) float g_obuf[NBATCH * LL * DD];
__device__ __align__(16) float g_kvb [NBATCH * LL * 512];
__device__ __align__(16) float g_qb  [2 * DD];

__device__ __forceinline__ float gelu_f(float x) {
    float x3 = x * x * x;
    float u = 0.7978845608028654f * (x + 0.044715f * x3);
    return 0.5f * x * (1.0f + tanhf(u));
}

// ---------------- prep kernels ----------------
__global__ void k_copy_emb(const float* __restrict__ ne, const float* __restrict__ te,
                           const float* __restrict__ ve) {
    size_t i = (size_t)blockIdx.x * 256 + threadIdx.x;
    float v;
    if (i < (size_t)NEURONS * DD)                 v = ne[i];
    else if (i < (size_t)(NEURONS + TBINS) * DD)  v = te[i - (size_t)NEURONS * DD];
    else                                          v = ve[i - (size_t)(NEURONS + TBINS) * DD];
    g_embcat[i] = v;
}

__global__ void k_rowstats() {
    __shared__ float red[16];
    int r = blockIdx.x, t = threadIdx.x;
    float x = g_embcat[(size_t)r * DD + t];
    float s = x, q = x * x;
#pragma unroll
    for (int o = 16; o > 0; o >>= 1) { s += __shfl_xor_sync(~0u, s, o); q += __shfl_xor_sync(~0u, q, o); }
    if ((t & 31) == 0) { red[t >> 5] = s; red[8 + (t >> 5)] = q; }
    __syncthreads();
    if (t == 0) {
        float ss = 0, qq = 0;
        for (int i = 0; i < 8; i++) { ss += red[i]; qq += red[8 + i]; }
        g_rowmean[r] = ss * (1.0f / DD);
        g_rowmsq[r]  = qq * (1.0f / DD);
    }
}

__global__ void k_ln(const float* __restrict__ in, float* __restrict__ out,
                     const float* __restrict__ w, const float* __restrict__ b) {
    __shared__ float red[16];
    int r = blockIdx.x, t = threadIdx.x;
    float x = in[(size_t)r * DD + t];
    float s = x, q = x * x;
#pragma unroll
    for (int o = 16; o > 0; o >>= 1) { s += __shfl_xor_sync(~0u, s, o); q += __shfl_xor_sync(~0u, q, o); }
    if ((t & 31) == 0) { red[t >> 5] = s; red[8 + (t >> 5)] = q; }
    __syncthreads();
    if (t == 0) {
        float ss = 0, qq = 0;
        for (int i = 0; i < 8; i++) { ss += red[i]; qq += red[8 + i]; }
        red[0] = ss; red[8] = qq;
    }
    __syncthreads();
    float mean = red[0] * (1.0f / DD);
    float var  = red[8] * (1.0f / DD) - mean * mean;
    float rstd = rsqrtf(var + 1e-5f);
    float y = (x - mean) * rstd;
    if (w) y = fmaf(y, w[t], b[t]);
    out[(size_t)r * DD + t] = y;
}

// q~[hl][i] = (ln(lat_init)[l] @ Wq_c)[h*32+i] * 32^-0.5,  hl = h*64+l
__global__ void k_q(const float* __restrict__ Wq) {
    __shared__ float xr[DD];
    int l = blockIdx.x, c = threadIdx.x;
    xr[c] = g_xl[l * DD + c];
    __syncthreads();
    float a0 = 0, a1 = 0, a2 = 0, a3 = 0;
#pragma unroll 4
    for (int d = 0; d < DD; d += 4) {
        a0 = fmaf(xr[d + 0], Wq[(d + 0) * DD + c], a0);
        a1 = fmaf(xr[d + 1], Wq[(d + 1) * DD + c], a1);
        a2 = fmaf(xr[d + 2], Wq[(d + 2) * DD + c], a2);
        a3 = fmaf(xr[d + 3], Wq[(d + 3) * DD + c], a3);
    }
    float a = (a0 + a1) + (a2 + a3);
    int h = c >> 5, i = c & 31;
    g_qh[((h << 6) + l) * 32 + i] = a * 0.17677669529663687f;
}

__global__ void k_colsum(const float* __restrict__ Wkv) {
    int j = blockIdx.x * 256 + threadIdx.x;
    float s = 0;
    for (int d = 0; d < DD; d++) s += Wkv[(size_t)d * 512 + j];
    g_colsum[j] = s;
    if (j >= 256) g_colV[j - 256] = s;
}

__global__ void k_qc() {
    int hl = threadIdx.x;
    int h = hl >> 6;
    float a = 0;
#pragma unroll
    for (int i = 0; i < 32; i++) a = fmaf(g_qh[hl * 32 + i], g_colsum[h * 32 + i], a);
    g_qcK[hl] = a;
}

// Wc[:, :512] = A (score projection folded with q),  Wc[:, 512:768] = Wkv V-part
__global__ void k_buildWc(const float* __restrict__ Wkv) {
    __shared__ float wr[256];
    int d = blockIdx.x, c = threadIdx.x;
    if (c < 256) wr[c] = Wkv[(size_t)d * 512 + c];
    __syncthreads();
    float out;
    if (c < 512) {
        int h = c >> 6;
        float a = 0;
#pragma unroll
        for (int i = 0; i < 32; i++) a = fmaf(wr[h * 32 + i], g_qh[c * 32 + i], a);
        out = a;
    } else {
        out = Wkv[(size_t)d * 512 + 256 + (c - 512)];
    }
    g_Wc[(size_t)d * 768 + c] = out;
}

// ---------------- fp32 GEMM, 128x128 tile, 8x8/thread ----------------
// flags: 1 = gelu, 2 = accumulate, 4 = split-store (bf16 g_Ts cols<512, fp32 g_Tv cols>=512)
__global__ void __launch_bounds__(256) k_gemm(const float* __restrict__ A, const float* __restrict__ W,
                                              float* __restrict__ C, int R, int K, int N, int flags) {
    __shared__ float As[16][132];
    __shared__ float Ws[16][132];
    int t = threadIdx.x;
    int rbase = blockIdx.x * 128, nbase = blockIdx.y * 128;
    int tr = t >> 4, tc = t & 15;
    float acc[8][8];
#pragma unroll
    for (int x = 0; x < 8; x++)
#pragma unroll
        for (int y = 0; y < 8; y++) acc[x][y] = 0.f;

    for (int k0 = 0; k0 < K; k0 += 16) {
#pragma unroll
        for (int j = 0; j < 2; j++) {
            int q = t * 2 + j;
            int m = q >> 2, k4 = (q & 3) * 4;
            int r = rbase + m;
            float4 av = make_float4(0.f, 0.f, 0.f, 0.f);
            if (r < R) av = *(const float4*)(A + (size_t)r * K + k0 + k4);
            As[k4 + 0][m] = av.x; As[k4 + 1][m] = av.y;
            As[k4 + 2][m] = av.z; As[k4 + 3][m] = av.w;
            int n4 = (q & 31) * 4, kw = q >> 5;
            float4 wv = *(const float4*)(W + (size_t)(k0 + kw) * N + nbase + n4);
            *(float4*)&Ws[kw][n4] = wv;
        }
        __syncthreads();
#pragma unroll
        for (int kk = 0; kk < 16; kk++) {
            float a[8], w[8];
#pragma unroll
            for (int x = 0; x < 8; x++) a[x] = As[kk][tr * 8 + x];
#pragma unroll
            for (int y = 0; y < 8; y++) w[y] = Ws[kk][tc * 8 + y];
#pragma unroll
            for (int x = 0; x < 8; x++)
#pragma unroll
                for (int y = 0; y < 8; y++) acc[x][y] = fmaf(a[x], w[y], acc[x][y]);
        }
        __syncthreads();
    }
#pragma unroll
    for (int x = 0; x < 8; x++) {
        int r = rbase + tr * 8 + x;
        if (r >= R) break;
        if (flags & 4) {
#pragma unroll
            for (int y = 0; y < 8; y++) {
                int cc = nbase + tc * 8 + y;
                float v = acc[x][y];
                if (cc < 512) g_Ts[(size_t)r * 512 + cc] = __float2bfloat16(v);
                else          g_Tv[(size_t)r * 256 + cc - 512] = v;
            }
        } else {
            float* crow = C + (size_t)r * N + nbase + tc * 8;
#pragma unroll
            for (int y = 0; y < 8; y++) {
                float v = acc[x][y];
                if (flags & 1) v = gelu_f(v);
                if (flags & 2) crow[y] += v; else crow[y] = v;
            }
        }
    }
}

// ---------------- fp32 GEMM, 64x64 tile, 4x4/thread (small latent GEMMs) ----------------
__global__ void __launch_bounds__(256) k_gemm64(const float* __restrict__ A, const float* __restrict__ W,
                                                float* __restrict__ C, int R, int K, int N, int flags) {
    __shared__ float As[16][68];
    __shared__ float Ws[16][68];
    int t = threadIdx.x;
    int rbase = blockIdx.x * 64, nbase = blockIdx.y * 64;
    int tr = t >> 4, tc = t & 15;
    float acc[4][4];
#pragma unroll
    for (int x = 0; x < 4; x++)
#pragma unroll
        for (int y = 0; y < 4; y++) acc[x][y] = 0.f;

    int ma = t >> 2, k4 = (t & 3) * 4;       // A: 64 rows x 16k
    int kw = t >> 4, n4 = (t & 15) * 4;      // W: 16k x 64n
    for (int k0 = 0; k0 < K; k0 += 16) {
        float4 av = make_float4(0.f, 0.f, 0.f, 0.f);
        if (rbase + ma < R) av = *(const float4*)(A + (size_t)(rbase + ma) * K + k0 + k4);
        As[k4 + 0][ma] = av.x; As[k4 + 1][ma] = av.y;
        As[k4 + 2][ma] = av.z; As[k4 + 3][ma] = av.w;
        float4 wv = *(const float4*)(W + (size_t)(k0 + kw) * N + nbase + n4);
        *(float4*)&Ws[kw][n4] = wv;
        __syncthreads();
#pragma unroll
        for (int kk = 0; kk < 16; kk++) {
            float4 a4 = *(const float4*)&As[kk][tr * 4];
            float4 w4 = *(const float4*)&Ws[kk][tc * 4];
            float a[4] = {a4.x, a4.y, a4.z, a4.w};
            float w[4] = {w4.x, w4.y, w4.z, w4.w};
#pragma unroll
            for (int x = 0; x < 4; x++)
#pragma unroll
                for (int y = 0; y < 4; y++) acc[x][y] = fmaf(a[x], w[y], acc[x][y]);
        }
        __syncthreads();
    }
#pragma unroll
    for (int x = 0; x < 4; x++) {
        int r = rbase + tr * 4 + x;
        if (r >= R) break;
        float* crow = C + (size_t)r * N + nbase + tc * 4;
#pragma unroll
        for (int y = 0; y < 4; y++) {
            float v = acc[x][y];
            if (flags & 1) v = gelu_f(v);
            if (flags & 2) crow[y] += v; else crow[y] = v;
        }
    }
}

// ---------------- deterministic event grouping (counting sort) ----------------
__global__ void k_count(const int* __restrict__ bix, int E) {
    __shared__ int sc[NBATCH];
    int c = blockIdx.x;
    if (threadIdx.x < NBATCH) sc[threadIdx.x] = 0;
    __syncthreads();
    int base = c << 10;
    for (int i = threadIdx.x; i < 1024; i += blockDim.x) {
        int e = base + i;
        if (e < E) atomicAdd(&sc[bix[e]], 1);
    }
    __syncthreads();
    if (threadIdx.x < NBATCH) g_chunkcnt[c * NBATCH + threadIdx.x] = sc[threadIdx.x];
}

__global__ void k_scan(int nch) {
    int b = threadIdx.x;
    if (b < NBATCH) {
        int run = 0;
        for (int c = 0; c < nch; c++) {
            int v = g_chunkcnt[c * NBATCH + b];
            g_chunkbase[c * NBATCH + b] = run;
            run += v;
        }
        g_cnt[b] = run;
    }
}

__global__ void k_scatter(const int* __restrict__ bix, int E) {
    __shared__ int loc[48];
    int c = blockIdx.x, lane = threadIdx.x;
    if (lane < NBATCH) loc[lane] = g_chunkbase[c * NBATCH + lane];
    loc[16 + lane] = 0;
    __syncwarp();
    int base = c << 10;
    for (int i = 0; i < 32; i++) {
        int e = base + i * 32 + lane;
        bool valid = e < E;
        int b_ = 0;
        if (valid) b_ = bix[e];
        int bb = valid ? b_ : 16 + lane;
        unsigned mm = __match_any_sync(0xffffffffu, bb);
        int rank = __popc(mm & ((1u << lane) - 1u));
        int leader = __ffs(mm) - 1;
        int start = 0;
        if (lane == leader) { start = loc[bb]; loc[bb] = start + __popc(mm); }
        start = __shfl_sync(0xffffffffu, start, leader);
        if (valid) g_evlist[b_ * EVSTRIDE + start + rank] = e;
        __syncwarp();
    }
}

// ---------------- per-event LN stats (float4 loads) ----------------
__global__ void k_stats(const int* __restrict__ nid, const int* __restrict__ tb,
                        const int* __restrict__ vl, int E) {
    int e = blockIdx.x * 8 + (threadIdx.x >> 5);
    int lane = threadIdx.x & 31;
    if (e >= E) return;
    int n = nid[e], t = tb[e], v = vl[e];
    const float4* rn = (const float4*)(g_embcat + (size_t)n * DD);
    const float4* rt = (const float4*)(g_embcat + (size_t)(NEURONS + t) * DD);
    const float4* rv = (const float4*)(g_embcat + (size_t)(NEURONS + TBINS + v) * DD);
    float dnt = 0, dnv = 0, dtv = 0;
#pragma unroll
    for (int d = 0; d < 2; d++) {
        int i = lane + d * 32;
        float4 a = rn[i], b = rt[i], c = rv[i];
        dnt = fmaf(a.x, b.x, fmaf(a.y, b.y, fmaf(a.z, b.z, fmaf(a.w, b.w, dnt))));
        dnv = fmaf(a.x, c.x, fmaf(a.y, c.y, fmaf(a.z, c.z, fmaf(a.w, c.w, dnv))));
        dtv = fmaf(b.x, c.x, fmaf(b.y, c.y, fmaf(b.z, c.z, fmaf(b.w, c.w, dtv))));
    }
#pragma unroll
    for (int o = 16; o > 0; o >>= 1) {
        dnt += __shfl_xor_sync(~0u, dnt, o);
        dnv += __shfl_xor_sync(~0u, dnv, o);
        dtv += __shfl_xor_sync(~0u, dtv, o);
    }
    if (lane == 0) {
        float m = g_rowmean[n] + g_rowmean[NEURONS + t] + g_rowmean[NEURONS + TBINS + v];
        float msq = g_rowmsq[n] + g_rowmsq[NEURONS + t] + g_rowmsq[NEURONS + TBINS + v]
                  + (dnt + dnv + dtv) * (2.0f / DD);
        float var = msq - m * m;
        g_me[e] = m;
        g_re[e] = rsqrtf(var + 1e-5f);
    }
}

// ---------------- fused ragged cross-attention ----------------
__global__ void __launch_bounds__(512, 1) k_cross(const int* __restrict__ nid,
                                                  const int* __restrict__ tb,
                                                  const int* __restrict__ vl) {
    int bs = blockIdx.x;
    int b = bs / NSPLIT, sp = bs - b * NSPLIT;
    int t = threadIdx.x;
    int cnt = g_cnt[b];
    if (cnt > EVSTRIDE) cnt = EVSTRIDE;
    int e0 = (int)((long long)cnt * sp / NSPLIT);
    int e1 = (int)((long long)cnt * (sp + 1) / NSPLIT);

    __shared__ float sv[8][256];
    float qc = g_qcK[t];
    float cv = (t < 256) ? g_colV[t] : 0.f;
    float acc[32];
#pragma unroll
    for (int i = 0; i < 32; i++) acc[i] = 0.f;
    float sumP = 0.f;
    int h32 = (t >> 6) << 5;
    const int* evl = g_evlist + b * EVSTRIDE;

    int base = e0;
    int endfull = e0 + (((e1 - e0) >> 3) << 3);
    for (; base < endfull; base += 8) {
        float p[8];
#pragma unroll
        for (int j = 0; j < 8; j++) {
            int e = evl[base + j];
            int n = nid[e], tt = tb[e], vv = vl[e];
            float m = g_me[e], r = g_re[e];
            float s = r * (__bfloat162float(g_Ts[(size_t)n * 512 + t])
                         + __bfloat162float(g_Ts[(size_t)(NEURONS + tt) * 512 + t])
                         + __bfloat162float(g_Ts[(size_t)(NEURONS + TBINS + vv) * 512 + t]))
                    - (r * m) * qc;
            p[j] = __expf(s);
            sumP += p[j];
            if (t < 256) {
                sv[j][t] = r * (g_Tv[(size_t)n * 256 + t]
                              + g_Tv[(size_t)(NEURONS + tt) * 256 + t]
                              + g_Tv[(size_t)(NEURONS + TBINS + vv) * 256 + t])
                         - (r * m) * cv;
            }
        }
        __syncthreads();
#pragma unroll
        for (int j = 0; j < 8; j++) {
            float pj = p[j];
            const float4* vp = (const float4*)(sv[j] + h32);
#pragma unroll
            for (int i = 0; i < 8; i++) {
                float4 v4 = vp[i];
                acc[4 * i + 0] = fmaf(pj, v4.x, acc[4 * i + 0]);
                acc[4 * i + 1] = fmaf(pj, v4.y, acc[4 * i + 1]);
                acc[4 * i + 2] = fmaf(pj, v4.z, acc[4 * i + 2]);
                acc[4 * i + 3] = fmaf(pj, v4.w, acc[4 * i + 3]);
            }
        }
        __syncthreads();
    }
    // tail (scalar, no register array)
    for (; base < e1; base++) {
        int e = evl[base];
        int n = nid[e], tt = tb[e], vv = vl[e];
        float m = g_me[e], r = g_re[e];
        float s = r * (__bfloat162float(g_Ts[(size_t)n * 512 + t])
                     + __bfloat162float(g_Ts[(size_t)(NEURONS + tt) * 512 + t])
                     + __bfloat162float(g_Ts[(size_t)(NEURONS + TBINS + vv) * 512 + t]))
                - (r * m) * qc;
        float p = __expf(s);
        sumP += p;
        if (t < 256) {
            sv[0][t] = r * (g_Tv[(size_t)n * 256 + t]
                          + g_Tv[(size_t)(NEURONS + tt) * 256 + t]
                          + g_Tv[(size_t)(NEURONS + TBINS + vv) * 256 + t])
                     - (r * m) * cv;
        }
        __syncthreads();
        const float4* vp = (const float4*)(sv[0] + h32);
#pragma unroll
        for (int i = 0; i < 8; i++) {
            float4 v4 = vp[i];
            acc[4 * i + 0] = fmaf(p, v4.x, acc[4 * i + 0]);
            acc[4 * i + 1] = fmaf(p, v4.y, acc[4 * i + 1]);
            acc[4 * i + 2] = fmaf(p, v4.z, acc[4 * i + 2]);
            acc[4 * i + 3] = fmaf(p, v4.w, acc[4 * i + 3]);
        }
        __syncthreads();
    }
    g_psum[(size_t)bs * HL + t] = sumP;
    float* pa = g_pacc + (size_t)bs * 32 * HL;
#pragma unroll
    for (int i = 0; i < 32; i++) pa[i * HL + t] = acc[i];
}

// grid (NBATCH, 32): block (b, channel i); threads = hl
__global__ void k_reduce() {
    int b = blockIdx.x, i = blockIdx.y, hl = threadIdx.x;
    float tot = 0;
#pragma unroll
    for (int s = 0; s < NSPLIT; s++) tot += g_psum[(size_t)(b * NSPLIT + s) * HL + hl];
    float inv = (tot > 0.f) ? 1.0f / tot : 0.f;
    float o = 0;
#pragma unroll
    for (int s = 0; s < NSPLIT; s++)
        o += g_pacc[(size_t)(b * NSPLIT + s) * 32 * HL + (size_t)i * HL + hl];
    int h = hl >> 6, l = hl & 63;
    g_attv[((size_t)(b * LL + l)) * DD + h * 32 + i] = o * inv;
}

__global__ void k_prefill(const float* __restrict__ lat0) {
    int row = blockIdx.x, t = threadIdx.x;
    g_lat[(size_t)row * DD + t] = lat0[(row & 63) * DD + t];
}

// ---------------- latent self-attention (per (b,h)) ----------------
__global__ void k_selfattn(const float* __restrict__ qkv, float* __restrict__ obuf) {
    int b = blockIdx.x >> 3, h = blockIdx.x & 7;
    __shared__ float qs[64][33], ks[64][33], vs[64][33], ps[64][65];
    int t = threadIdx.x;
    for (int id = t; id < 64 * 32; id += 256) {
        int l = id >> 5, i = id & 31;
        const float* base = qkv + ((size_t)(b * LL + l)) * 768 + h * 32 + i;
        qs[l][i] = base[0];
        ks[l][i] = base[256];
        vs[l][i] = base[512];
    }
    __syncthreads();
    int ql = t >> 2, k0 = (t & 3) * 16;
    for (int kk = 0; kk < 16; kk++) {
        int k = k0 + kk;
        float s = 0;
#pragma unroll
        for (int d = 0; d < 32; d++) s = fmaf(qs[ql][d], ks[k][d], s);
        ps[ql][k] = s * 0.17677669529663687f;
    }
    __syncthreads();
    if (t < 64) {
        float mx = -1e30f;
        for (int k = 0; k < 64; k++) mx = fmaxf(mx, ps[t][k]);
        float sum = 0;
        for (int k = 0; k < 64; k++) { float p = __expf(ps[t][k] - mx); ps[t][k] = p; sum += p; }
        float inv = 1.0f / sum;
        for (int k = 0; k < 64; k++) ps[t][k] *= inv;
    }
    __syncthreads();
    int i = t & 31, l0 = t >> 5;
    for (int j = 0; j < 8; j++) {
        int l = l0 + j * 8;
        float o = 0;
        for (int k = 0; k < 64; k++) o = fmaf(ps[l][k], vs[k][i], o);
        obuf[((size_t)(b * LL + l)) * DD + h * 32 + i] = o;
    }
}

// ---------------- behavior decoder + logits ----------------
__global__ void k_behav(const float* __restrict__ bh_wo, float* __restrict__ out) {
    int b = blockIdx.x, t = threadIdx.x;
    __shared__ float sc[16][65];
    __shared__ float ov[2][256];
    __shared__ float red[8];
    for (int id = t; id < 1024; id += 256) {
        int jh = id >> 6, k = id & 63;
        int j = jh >> 3, h = jh & 7;
        const float* kr = g_kvb + ((size_t)(b * LL + k)) * 512 + h * 32;
        const float* qr = g_qb + j * DD + h * 32;
        float s = 0;
#pragma unroll
        for (int d = 0; d < 32; d++) s = fmaf(qr[d], kr[d], s);
        sc[jh][k] = s * 0.17677669529663687f;
    }
    __syncthreads();
    if (t < 16) {
        float mx = -1e30f;
        for (int k = 0; k < 64; k++) mx = fmaxf(mx, sc[t][k]);
        float sum = 0;
        for (int k = 0; k < 64; k++) { float p = __expf(sc[t][k] - mx); sc[t][k] = p; sum += p; }
        float inv = 1.0f / sum;
        for (int k = 0; k < 64; k++) sc[t][k] *= inv;
    }
    __syncthreads();
    for (int id = t; id < 512; id += 256) {
        int j = id >> 8, c = id & 255, h = c >> 5;
        float o = 0;
        for (int k = 0; k < 64; k++)
            o = fmaf(sc[j * 8 + h][k], g_kvb[((size_t)(b * LL + k)) * 512 + 256 + c], o);
        ov[j][c] = o;
    }
    __syncthreads();
    for (int j = 0; j < 2; j++) {
        float v = ov[j][t] * bh_wo[t];
#pragma unroll
        for (int o = 16; o > 0; o >>= 1) v += __shfl_xor_sync(~0u, v, o);
        if ((t & 31) == 0) red[t >> 5] = v;
        __syncthreads();
        if (t == 0) {
            float s = 0;
            for (int w = 0; w < 8; w++) s += red[w];
            out[b * 2 + j] = s;
        }
        __syncthreads();
    }
}

__global__ void k_logits(const float* __restrict__ sp_w, const float* __restrict__ sp_b,
                         float* __restrict__ out) {
    int b = blockIdx.x, t = threadIdx.x;
    __shared__ float mean[DD];
    float s = 0;
    for (int l = 0; l < LL; l++) s += g_lat[((size_t)(b * LL + l)) * DD + t];
    mean[t] = s * (1.0f / LL);
    __syncthreads();
    if (t < 64) {
        float a = sp_b[t];
        for (int d = 0; d < DD; d++) a = fmaf(mean[d], sp_w[d * 64 + t], a);
        out[32 + b * 64 + t] = a;
    }
}

// ---------------- host driver ----------------
extern "C" void kernel_launch(void* const* d_in, const int* in_sizes, int n_in,
                              void* d_out, int out_size) {
    const float* W[21];
    int wi = 0;
    const int* ids[4] = {nullptr, nullptr, nullptr, nullptr};
    int E = 0;
    for (int i = 0; i < n_in; i++) {
        int s = in_sizes[i];
        if (s <= 2) continue;
        if (!E && s >= 50000 && i + 3 < n_in && in_sizes[i + 1] == s &&
            in_sizes[i + 2] == s && in_sizes[i + 3] == s) {
            for (int j = 0; j < 4; j++) ids[j] = (const int*)d_in[i + j];
            E = s;
            i += 3;
            continue;
        }
        if (wi < 21) W[wi++] = (const float*)d_in[i];
    }
    const float *ne = W[0], *te = W[1], *ve = W[2], *lat0 = W[3], *Wq = W[4], *Wkv = W[5],
                *Wo = W[6], *W1 = W[7], *W2 = W[8], *Wqkv_s = W[9], *Wo_s = W[10],
                *W1_s = W[11], *W2_s = W[12], *bhq = W[13], *bhwq = W[14], *bhwkv = W[15],
                *bhwo = W[16], *lnw = W[17], *lnb = W[18], *spw = W[19], *spb = W[20];
    const int *nid = ids[0], *tbv = ids[1], *vlv = ids[2], *bix = ids[3];
    float* out = (float*)d_out;

    float *p_embcat, *p_Wc, *p_xl, *p_x, *p_h, *p_lat, *p_qkv, *p_obuf, *p_kvb, *p_qb, *p_attv;
    cudaGetSymbolAddress((void**)&p_embcat, g_embcat);
    cudaGetSymbolAddress((void**)&p_Wc, g_Wc);
    cudaGetSymbolAddress((void**)&p_xl, g_xl);
    cudaGetSymbolAddress((void**)&p_x, g_x);
    cudaGetSymbolAddress((void**)&p_h, g_h);
    cudaGetSymbolAddress((void**)&p_lat, g_lat);
    cudaGetSymbolAddress((void**)&p_qkv, g_qkv);
    cudaGetSymbolAddress((void**)&p_obuf, g_obuf);
    cudaGetSymbolAddress((void**)&p_kvb, g_kvb);
    cudaGetSymbolAddress((void**)&p_qb, g_qb);
    cudaGetSymbolAddress((void**)&p_attv, g_attv);

    int nch = (E + 1023) >> 10;

    // --- precompute tables ---
    k_copy_emb<<<NROWS, 256>>>(ne, te, ve);
    k_rowstats<<<NROWS, 256>>>();
    k_ln<<<64, 256>>>(lat0, p_xl, nullptr, nullptr);
    k_q<<<64, 256>>>(Wq);
    k_colsum<<<2, 256>>>(Wkv);
    k_qc<<<1, 512>>>();
    k_buildWc<<<256, 768>>>(Wkv);
    {
        dim3 g(42, 6);
        k_gemm<<<g, 256>>>(p_embcat, p_Wc, nullptr, NROWS, 256, 768, 4);
    }

    // --- event grouping + stats ---
    k_count<<<nch, 256>>>(bix, E);
    k_scan<<<1, 16>>>(nch);
    k_scatter<<<nch, 32>>>(bix, E);
    k_stats<<<(E + 7) / 8, 256>>>(nid, tbv, vlv, E);

    // --- fused cross attention ---
    k_cross<<<NBATCH * NSPLIT, 512>>>(nid, tbv, vlv);
    { dim3 g(NBATCH, 32); k_reduce<<<g, 512>>>(); }

    // --- latent pipeline ---
    k_prefill<<<NBATCH * LL, 256>>>(lat0);
    { dim3 g(16, 4);  k_gemm64<<<g, 256>>>(p_attv, Wo, p_lat, 1024, 256, 256, 2); }
    k_ln<<<1024, 256>>>(p_lat, p_x, nullptr, nullptr);
    { dim3 g(16, 16); k_gemm64<<<g, 256>>>(p_x, W1, p_h, 1024, 256, 1024, 1); }
    { dim3 g(16, 4);  k_gemm64<<<g, 256>>>(p_h, W2, p_lat, 1024, 1024, 256, 2); }

    for (int i = 0; i < 2; i++) {
        k_ln<<<1024, 256>>>(p_lat, p_x, nullptr, nullptr);
        { dim3 g(16, 12); k_gemm64<<<g, 256>>>(p_x, Wqkv_s + (size_t)i * 256 * 768, p_qkv, 1024, 256, 768, 0); }
        k_selfattn<<<NBATCH * 8, 256>>>(p_qkv, p_obuf);
        { dim3 g(16, 4);  k_gemm64<<<g, 256>>>(p_obuf, Wo_s + (size_t)i * 256 * 256, p_lat, 1024, 256, 256, 2); }
        k_ln<<<1024, 256>>>(p_lat, p_x, nullptr, nullptr);
        { dim3 g(16, 16); k_gemm64<<<g, 256>>>(p_x, W1_s + (size_t)i * 256 * 1024, p_h, 1024, 256, 1024, 1); }
        { dim3 g(16, 4);  k_gemm64<<<g, 256>>>(p_h, W2_s + (size_t)i * 1024 * 256, p_lat, 1024, 1024, 256, 2); }
    }

    // --- behavior decoder ---
    k_ln<<<1024, 256>>>(p_lat, p_x, lnw, lnb);
    { dim3 g(16, 8); k_gemm64<<<g, 256>>>(p_x, bhwkv, p_kvb, 1024, 256, 512, 0); }
    { dim3 g(1, 4);  k_gemm64<<<g, 256>>>(bhq, bhwq, p_qb, 2, 256, 256, 0); }
    k_behav<<<NBATCH, 256>>>(bhwo, out);

    // --- spike logits ---
    k_logits<<<NBATCH, 256>>>(spw, spb, out);
}

// round 7
// speedup vs baseline: 1.2989x; 1.0332x over previous
#include <cuda_runtime.h>
#include <cuda_bf16.h>
#include <cstddef>

#define DD 256
#define HH 8
#define LL 64
#define HL 512
#define NEURONS 4096
#define TBINS 1024
#define VBUCK 256
#define NBATCH 16
#define EVSTRIDE 13600
#define MAXE 200704
#define NSPLIT 9
#define NROWS 5376

// ---------------- static device scratch ----------------
__device__ __align__(16) float g_embcat[NROWS * DD];
__device__ float g_rowmean[NROWS];
__device__ float g_rowmsq[NROWS];
__device__ __align__(16) float g_xl[LL * DD];
__device__ __align__(16) float g_qh[HL * 32];
__device__ float g_colsum[512];
__device__ __align__(8) float g_colV[256];
__device__ __align__(8) float g_qcK[HL];
__device__ __align__(16) float g_Wc[DD * 768];
__device__ __align__(16) __nv_bfloat16 g_Ts[NROWS * 512];   // bf16 score table
__device__ __align__(16) float g_Tv[NROWS * 256];           // fp32 V table
__device__ float g_me[MAXE];
__device__ float g_re[MAXE];
__device__ int   g_cnt[NBATCH];
__device__ int   g_chunkcnt[256 * NBATCH];
__device__ int   g_chunkbase[256 * NBATCH];
__device__ int   g_evlist[NBATCH * EVSTRIDE];
__device__ __align__(8) float g_psum[NBATCH * NSPLIT * HL];
__device__ float g_pacc[NBATCH * NSPLIT * 32 * HL];
__device__ __align__(16) float g_attv[NBATCH * LL * DD];
__device__ __align__(16) float g_lat [NBATCH * LL * DD];
__device__ __align__(16) float g_h   [NBATCH * LL * 1024];
__device__ __align__(16) float g_qkv [NBATCH * LL * 768];
__device__ __align__(16) float g_obuf[NBATCH * LL * DD];
__device__ __align__(16) float g_kvb [NBATCH * LL * 512];
__device__ __align__(16) float g_qb  [2 * DD];
__device__ float g_lnm[NBATCH * LL];
__device__ float g_lnr[NBATCH * LL];

// ---------------- f32x2 helpers ----------------
__device__ __forceinline__ void fma2(unsigned long long& d, unsigned long long a, unsigned long long b) {
    asm("fma.rn.f32x2 %0, %1, %2, %0;" : "+l"(d) : "l"(a), "l"(b));
}
__device__ __forceinline__ unsigned long long pk2(float x, float y) {
    unsigned long long r;
    asm("mov.b64 %0, {%1, %2};" : "=l"(r) : "f"(x), "f"(y));
    return r;
}
__device__ __forceinline__ void upk2(float& x, float& y, unsigned long long r) {
    asm("mov.b64 {%0, %1}, %2;" : "=f"(x), "=f"(y) : "l"(r));
}

__device__ __forceinline__ float gelu_f(float x) {
    float x3 = x * x * x;
    float u = 0.7978845608028654f * (x + 0.044715f * x3);
    return 0.5f * x * (1.0f + tanhf(u));
}

// ---------------- prep kernels ----------------
__global__ void k_copy_emb(const float* __restrict__ ne, const float* __restrict__ te,
                           const float* __restrict__ ve) {
    size_t i = (size_t)blockIdx.x * 256 + threadIdx.x;
    float v;
    if (i < (size_t)NEURONS * DD)                 v = ne[i];
    else if (i < (size_t)(NEURONS + TBINS) * DD)  v = te[i - (size_t)NEURONS * DD];
    else                                          v = ve[i - (size_t)(NEURONS + TBINS) * DD];
    g_embcat[i] = v;
}

__global__ void k_rowstats() {
    __shared__ float red[16];
    int r = blockIdx.x, t = threadIdx.x;
    float x = g_embcat[(size_t)r * DD + t];
    float s = x, q = x * x;
#pragma unroll
    for (int o = 16; o > 0; o >>= 1) { s += __shfl_xor_sync(~0u, s, o); q += __shfl_xor_sync(~0u, q, o); }
    if ((t & 31) == 0) { red[t >> 5] = s; red[8 + (t >> 5)] = q; }
    __syncthreads();
    if (t == 0) {
        float ss = 0, qq = 0;
        for (int i = 0; i < 8; i++) { ss += red[i]; qq += red[8 + i]; }
        g_rowmean[r] = ss * (1.0f / DD);
        g_rowmsq[r]  = qq * (1.0f / DD);
    }
}

__global__ void k_ln(const float* __restrict__ in, float* __restrict__ out) {
    __shared__ float red[16];
    int r = blockIdx.x, t = threadIdx.x;
    float x = in[(size_t)r * DD + t];
    float s = x, q = x * x;
#pragma unroll
    for (int o = 16; o > 0; o >>= 1) { s += __shfl_xor_sync(~0u, s, o); q += __shfl_xor_sync(~0u, q, o); }
    if ((t & 31) == 0) { red[t >> 5] = s; red[8 + (t >> 5)] = q; }
    __syncthreads();
    if (t == 0) {
        float ss = 0, qq = 0;
        for (int i = 0; i < 8; i++) { ss += red[i]; qq += red[8 + i]; }
        red[0] = ss; red[8] = qq;
    }
    __syncthreads();
    float mean = red[0] * (1.0f / DD);
    float var  = red[8] * (1.0f / DD) - mean * mean;
    float rstd = rsqrtf(var + 1e-5f);
    out[(size_t)r * DD + t] = (x - mean) * rstd;
}

// per-row mean/rstd for LN-fused GEMM (8 rows/block, warp per row)
__global__ void k_lnstats(const float* __restrict__ A, int R) {
    int r = blockIdx.x * 8 + (threadIdx.x >> 5);
    int lane = threadIdx.x & 31;
    if (r >= R) return;
    const float4* a4 = (const float4*)(A + (size_t)r * DD);
    float s = 0, q = 0;
#pragma unroll
    for (int d = 0; d < 2; d++) {
        float4 v = a4[lane + 32 * d];
        s += v.x + v.y + v.z + v.w;
        q = fmaf(v.x, v.x, fmaf(v.y, v.y, fmaf(v.z, v.z, fmaf(v.w, v.w, q))));
    }
#pragma unroll
    for (int o = 16; o > 0; o >>= 1) { s += __shfl_xor_sync(~0u, s, o); q += __shfl_xor_sync(~0u, q, o); }
    if (lane == 0) {
        float mean = s * (1.0f / DD);
        float var = q * (1.0f / DD) - mean * mean;
        g_lnm[r] = mean;
        g_lnr[r] = rsqrtf(var + 1e-5f);
    }
}

// q~[hl][i] = (ln(lat_init)[l] @ Wq_c)[h*32+i] * 32^-0.5,  hl = h*64+l
__global__ void k_q(const float* __restrict__ Wq) {
    __shared__ float xr[DD];
    int l = blockIdx.x, c = threadIdx.x;
    xr[c] = g_xl[l * DD + c];
    __syncthreads();
    float a0 = 0, a1 = 0, a2 = 0, a3 = 0;
#pragma unroll 4
    for (int d = 0; d < DD; d += 4) {
        a0 = fmaf(xr[d + 0], Wq[(d + 0) * DD + c], a0);
        a1 = fmaf(xr[d + 1], Wq[(d + 1) * DD + c], a1);
        a2 = fmaf(xr[d + 2], Wq[(d + 2) * DD + c], a2);
        a3 = fmaf(xr[d + 3], Wq[(d + 3) * DD + c], a3);
    }
    float a = (a0 + a1) + (a2 + a3);
    int h = c >> 5, i = c & 31;
    g_qh[((h << 6) + l) * 32 + i] = a * 0.17677669529663687f;
}

__global__ void k_colsum(const float* __restrict__ Wkv) {
    int j = blockIdx.x * 256 + threadIdx.x;
    float s = 0;
    for (int d = 0; d < DD; d++) s += Wkv[(size_t)d * 512 + j];
    g_colsum[j] = s;
    if (j >= 256) g_colV[j - 256] = s;
}

__global__ void k_qc() {
    int hl = threadIdx.x;
    int h = hl >> 6;
    float a = 0;
#pragma unroll
    for (int i = 0; i < 32; i++) a = fmaf(g_qh[hl * 32 + i], g_colsum[h * 32 + i], a);
    g_qcK[hl] = a;
}

// Wc[:, :512] = A (score projection folded with q),  Wc[:, 512:768] = Wkv V-part
__global__ void k_buildWc(const float* __restrict__ Wkv) {
    __shared__ float wr[256];
    int d = blockIdx.x, c = threadIdx.x;
    if (c < 256) wr[c] = Wkv[(size_t)d * 512 + c];
    __syncthreads();
    float out;
    if (c < 512) {
        int h = c >> 6;
        float a = 0;
#pragma unroll
        for (int i = 0; i < 32; i++) a = fmaf(wr[h * 32 + i], g_qh[c * 32 + i], a);
        out = a;
    } else {
        out = Wkv[(size_t)d * 512 + 256 + (c - 512)];
    }
    g_Wc[(size_t)d * 768 + c] = out;
}

// ---------------- fp32 GEMM, 128x128 tile, 8x8/thread, f32x2 FMA ----------------
// flags: 4 = split-store (bf16 g_Ts cols<512, fp32 g_Tv cols>=512)
__global__ void __launch_bounds__(256) k_gemm(const float* __restrict__ A, const float* __restrict__ W,
                                              float* __restrict__ C, int R, int K, int N, int flags) {
    __shared__ float As[16][132];
    __shared__ float Ws[16][132];
    int t = threadIdx.x;
    int rbase = blockIdx.x * 128, nbase = blockIdx.y * 128;
    int tr = t >> 4, tc = t & 15;
    unsigned long long acc2[8][4];
#pragma unroll
    for (int x = 0; x < 8; x++)
#pragma unroll
        for (int y = 0; y < 4; y++) acc2[x][y] = 0ull;

    for (int k0 = 0; k0 < K; k0 += 16) {
#pragma unroll
        for (int j = 0; j < 2; j++) {
            int q = t * 2 + j;
            int m = q >> 2, k4 = (q & 3) * 4;
            int r = rbase + m;
            float4 av = make_float4(0.f, 0.f, 0.f, 0.f);
            if (r < R) av = *(const float4*)(A + (size_t)r * K + k0 + k4);
            As[k4 + 0][m] = av.x; As[k4 + 1][m] = av.y;
            As[k4 + 2][m] = av.z; As[k4 + 3][m] = av.w;
            int n4 = (q & 31) * 4, kw = q >> 5;
            float4 wv = *(const float4*)(W + (size_t)(k0 + kw) * N + nbase + n4);
            *(float4*)&Ws[kw][n4] = wv;
        }
        __syncthreads();
#pragma unroll
        for (int kk = 0; kk < 16; kk++) {
            float4 aA = *(const float4*)&As[kk][tr * 8];
            float4 aB = *(const float4*)&As[kk][tr * 8 + 4];
            ulonglong2 w0 = *(const ulonglong2*)&Ws[kk][tc * 8];
            ulonglong2 w1 = *(const ulonglong2*)&Ws[kk][tc * 8 + 4];
            float a[8] = {aA.x, aA.y, aA.z, aA.w, aB.x, aB.y, aB.z, aB.w};
#pragma unroll
            for (int x = 0; x < 8; x++) {
                unsigned long long aa = pk2(a[x], a[x]);
                fma2(acc2[x][0], aa, w0.x);
                fma2(acc2[x][1], aa, w0.y);
                fma2(acc2[x][2], aa, w1.x);
                fma2(acc2[x][3], aa, w1.y);
            }
        }
        __syncthreads();
    }
#pragma unroll
    for (int x = 0; x < 8; x++) {
        int r = rbase + tr * 8 + x;
        if (r >= R) break;
        float v[8];
#pragma unroll
        for (int y = 0; y < 4; y++) upk2(v[2 * y], v[2 * y + 1], acc2[x][y]);
        if (flags & 4) {
#pragma unroll
            for (int y = 0; y < 8; y++) {
                int cc = nbase + tc * 8 + y;
                if (cc < 512) g_Ts[(size_t)r * 512 + cc] = __float2bfloat16(v[y]);
                else          g_Tv[(size_t)r * 256 + cc - 512] = v[y];
            }
        } else {
            float* crow = C + (size_t)r * N + nbase + tc * 8;
#pragma unroll
            for (int y = 0; y < 8; y++) crow[y] = v[y];
        }
    }
}

// ---------------- fp32 GEMM, 64x64 tile, 4x4/thread, f32x2 FMA ----------------
// flags: 1 = gelu, 2 = accumulate, 8 = LN on A rows (g_lnm/g_lnr; optional affine lw/lb)
__global__ void __launch_bounds__(256) k_gemm64(const float* __restrict__ A, const float* __restrict__ W,
                                                float* __restrict__ C, int R, int K, int N, int flags,
                                                const float* __restrict__ lw, const float* __restrict__ lb) {
    __shared__ float As[16][68];
    __shared__ float Ws[16][68];
    int t = threadIdx.x;
    int rbase = blockIdx.x * 64, nbase = blockIdx.y * 64;
    int tr = t >> 4, tc = t & 15;
    unsigned long long acc2[4][2];
#pragma unroll
    for (int x = 0; x < 4; x++) { acc2[x][0] = 0ull; acc2[x][1] = 0ull; }

    int ma = t >> 2, k4 = (t & 3) * 4;       // A: 64 rows x 16k
    int kw = t >> 4, n4 = (t & 15) * 4;      // W: 16k x 64n
    int arow = rbase + ma;
    float lm = 0.f, lr = 1.f;
    if ((flags & 8) && arow < R) { lm = g_lnm[arow]; lr = g_lnr[arow]; }

    for (int k0 = 0; k0 < K; k0 += 16) {
        float4 av = make_float4(0.f, 0.f, 0.f, 0.f);
        if (arow < R) av = *(const float4*)(A + (size_t)arow * K + k0 + k4);
        if (flags & 8) {
            av.x = (av.x - lm) * lr; av.y = (av.y - lm) * lr;
            av.z = (av.z - lm) * lr; av.w = (av.w - lm) * lr;
            if (lw) {
                float4 w4 = *(const float4*)(lw + k0 + k4);
                float4 b4 = *(const float4*)(lb + k0 + k4);
                av.x = fmaf(av.x, w4.x, b4.x); av.y = fmaf(av.y, w4.y, b4.y);
                av.z = fmaf(av.z, w4.z, b4.z); av.w = fmaf(av.w, w4.w, b4.w);
            }
        }
        As[k4 + 0][ma] = av.x; As[k4 + 1][ma] = av.y;
        As[k4 + 2][ma] = av.z; As[k4 + 3][ma] = av.w;
        float4 wv = *(const float4*)(W + (size_t)(k0 + kw) * N + nbase + n4);
        *(float4*)&Ws[kw][n4] = wv;
        __syncthreads();
#pragma unroll
        for (int kk = 0; kk < 16; kk++) {
            float4 a4 = *(const float4*)&As[kk][tr * 4];
            ulonglong2 w2 = *(const ulonglong2*)&Ws[kk][tc * 4];
            float a[4] = {a4.x, a4.y, a4.z, a4.w};
#pragma unroll
            for (int x = 0; x < 4; x++) {
                unsigned long long aa = pk2(a[x], a[x]);
                fma2(acc2[x][0], aa, w2.x);
                fma2(acc2[x][1], aa, w2.y);
            }
        }
        __syncthreads();
    }
#pragma unroll
    for (int x = 0; x < 4; x++) {
        int r = rbase + tr * 4 + x;
        if (r >= R) break;
        float v[4];
        upk2(v[0], v[1], acc2[x][0]);
        upk2(v[2], v[3], acc2[x][1]);
        float* crow = C + (size_t)r * N + nbase + tc * 4;
#pragma unroll
        for (int y = 0; y < 4; y++) {
            float vv = v[y];
            if (flags & 1) vv = gelu_f(vv);
            if (flags & 2) crow[y] += vv; else crow[y] = vv;
        }
    }
}

// ---------------- deterministic event grouping (counting sort) ----------------
__global__ void k_count(const int* __restrict__ bix, int E) {
    __shared__ int sc[NBATCH];
    int c = blockIdx.x;
    if (threadIdx.x < NBATCH) sc[threadIdx.x] = 0;
    __syncthreads();
    int base = c << 10;
    for (int i = threadIdx.x; i < 1024; i += blockDim.x) {
        int e = base + i;
        if (e < E) atomicAdd(&sc[bix[e]], 1);
    }
    __syncthreads();
    if (threadIdx.x < NBATCH) g_chunkcnt[c * NBATCH + threadIdx.x] = sc[threadIdx.x];
}

__global__ void k_scan(int nch) {
    int b = threadIdx.x;
    if (b < NBATCH) {
        int run = 0;
        for (int c = 0; c < nch; c++) {
            int v = g_chunkcnt[c * NBATCH + b];
            g_chunkbase[c * NBATCH + b] = run;
            run += v;
        }
        g_cnt[b] = run;
    }
}

__global__ void k_scatter(const int* __restrict__ bix, int E) {
    __shared__ int loc[48];
    int c = blockIdx.x, lane = threadIdx.x;
    if (lane < NBATCH) loc[lane] = g_chunkbase[c * NBATCH + lane];
    loc[16 + lane] = 0;
    __syncwarp();
    int base = c << 10;
    for (int i = 0; i < 32; i++) {
        int e = base + i * 32 + lane;
        bool valid = e < E;
        int b_ = 0;
        if (valid) b_ = bix[e];
        int bb = valid ? b_ : 16 + lane;
        unsigned mm = __match_any_sync(0xffffffffu, bb);
        int rank = __popc(mm & ((1u << lane) - 1u));
        int leader = __ffs(mm) - 1;
        int start = 0;
        if (lane == leader) { start = loc[bb]; loc[bb] = start + __popc(mm); }
        start = __shfl_sync(0xffffffffu, start, leader);
        if (valid) g_evlist[b_ * EVSTRIDE + start + rank] = e;
        __syncwarp();
    }
}

// ---------------- per-event LN stats ----------------
__global__ void k_stats(const int* __restrict__ nid, const int* __restrict__ tb,
                        const int* __restrict__ vl, int E) {
    int e = blockIdx.x * 8 + (threadIdx.x >> 5);
    int lane = threadIdx.x & 31;
    if (e >= E) return;
    int n = nid[e], t = tb[e], v = vl[e];
    const float4* rn = (const float4*)(g_embcat + (size_t)n * DD);
    const float4* rt = (const float4*)(g_embcat + (size_t)(NEURONS + t) * DD);
    const float4* rv = (const float4*)(g_embcat + (size_t)(NEURONS + TBINS + v) * DD);
    float dnt = 0, dnv = 0, dtv = 0;
#pragma unroll
    for (int d = 0; d < 2; d++) {
        int i = lane + d * 32;
        float4 a = rn[i], b = rt[i], c = rv[i];
        dnt = fmaf(a.x, b.x, fmaf(a.y, b.y, fmaf(a.z, b.z, fmaf(a.w, b.w, dnt))));
        dnv = fmaf(a.x, c.x, fmaf(a.y, c.y, fmaf(a.z, c.z, fmaf(a.w, c.w, dnv))));
        dtv = fmaf(b.x, c.x, fmaf(b.y, c.y, fmaf(b.z, c.z, fmaf(b.w, c.w, dtv))));
    }
#pragma unroll
    for (int o = 16; o > 0; o >>= 1) {
        dnt += __shfl_xor_sync(~0u, dnt, o);
        dnv += __shfl_xor_sync(~0u, dnv, o);
        dtv += __shfl_xor_sync(~0u, dtv, o);
    }
    if (lane == 0) {
        float m = g_rowmean[n] + g_rowmean[NEURONS + t] + g_rowmean[NEURONS + TBINS + v];
        float msq = g_rowmsq[n] + g_rowmsq[NEURONS + t] + g_rowmsq[NEURONS + TBINS + v]
                  + (dnt + dnv + dtv) * (2.0f / DD);
        float var = msq - m * m;
        g_me[e] = m;
        g_re[e] = rsqrtf(var + 1e-5f);
    }
}

// ---------------- fused ragged cross-attention ----------------
// t<256: scores (bf16x2 pairs, hl=2t,2t+1); t in [256,384): V channels (2u,2u+1);
// all 512: accumulate hl=t with f32x2 FMA. Metadata double-buffered in smem.
__global__ void __launch_bounds__(512, 1) k_cross(const int* __restrict__ nid,
                                                  const int* __restrict__ tb,
                                                  const int* __restrict__ vl) {
    int bs = blockIdx.x;
    int b = bs / NSPLIT, sp = bs - b * NSPLIT;
    int t = threadIdx.x;
    int cnt = g_cnt[b];
    if (cnt > EVSTRIDE) cnt = EVSTRIDE;
    int e0 = (int)((long long)cnt * sp / NSPLIT);
    int e1 = (int)((long long)cnt * (sp + 1) / NSPLIT);

    __shared__ float sv[8][256];
    __shared__ float ps[8][512];
    __shared__ int4  sMeta[2][8];
    __shared__ float sR[2][8];

    const __nv_bfloat162* __restrict__ Ts2 = (const __nv_bfloat162*)g_Ts;
    const float2* __restrict__ Tv2 = (const float2*)g_Tv;

    float2 qc2 = make_float2(0.f, 0.f);
    float2 cv2 = make_float2(0.f, 0.f);
    if (t < 256) qc2 = *(const float2*)&g_qcK[2 * t];
    else if (t < 384) cv2 = *(const float2*)&g_colV[2 * (t - 256)];

    unsigned long long acc[16];
#pragma unroll
    for (int i = 0; i < 16; i++) acc[i] = 0ull;
    float sum0 = 0.f, sum1 = 0.f;
    int h32 = (t >> 6) << 5;
    const int* evl = g_evlist + b * EVSTRIDE;

    // preload batch 0 metadata
    if (t < 8 && e0 + t < e1) {
        int e = evl[e0 + t];
        int n_ = nid[e], tt_ = tb[e], vv_ = vl[e];
        float r_ = g_re[e], m_ = g_me[e];
        sMeta[0][t] = make_int4(n_, NEURONS + tt_, NEURONS + TBINS + vv_, __float_as_int(-r_ * m_));
        sR[0][t] = r_;
    }
    __syncthreads();

    int cur = 0;
    for (int base = e0; base < e1; base += 8, cur ^= 1) {
        int nb = min(8, e1 - base);
        // prefetch next batch metadata into registers
        bool pf = (t < 8) && (base + 8 + t < e1);
        int4 pm; float pr = 0.f;
        if (pf) {
            int e = evl[base + 8 + t];
            int n_ = nid[e], tt_ = tb[e], vv_ = vl[e];
            float r_ = g_re[e], m_ = g_me[e];
            pm = make_int4(n_, NEURONS + tt_, NEURONS + TBINS + vv_, __float_as_int(-r_ * m_));
            pr = r_;
        }
        // score / V phase
        if (t < 256) {
            for (int j = 0; j < nb; j++) {
                int4 mm = sMeta[cur][j];
                float r = sR[cur][j];
                float rm = __int_as_float(mm.w);
                float2 fa = __bfloat1622float2(Ts2[(size_t)mm.x * 256 + t]);
                float2 fb = __bfloat1622float2(Ts2[(size_t)mm.y * 256 + t]);
                float2 fc = __bfloat1622float2(Ts2[(size_t)mm.z * 256 + t]);
                float s0 = fmaf(r, fa.x + fb.x + fc.x, rm * qc2.x);
                float s1 = fmaf(r, fa.y + fb.y + fc.y, rm * qc2.y);
                float p0 = __expf(s0), p1 = __expf(s1);
                sum0 += p0; sum1 += p1;
                *(float2*)&ps[j][2 * t] = make_float2(p0, p1);
            }
        } else if (t < 384) {
            int u = t - 256;
            for (int j = 0; j < nb; j++) {
                int4 mm = sMeta[cur][j];
                float r = sR[cur][j];
                float rm = __int_as_float(mm.w);
                float2 va = Tv2[(size_t)mm.x * 128 + u];
                float2 vb = Tv2[(size_t)mm.y * 128 + u];
                float2 vc = Tv2[(size_t)mm.z * 128 + u];
                float2 o;
                o.x = fmaf(r, va.x + vb.x + vc.x, rm * cv2.x);
                o.y = fmaf(r, va.y + vb.y + vc.y, rm * cv2.y);
                *(float2*)&sv[j][2 * u] = o;
            }
        }
        __syncthreads();
        // store prefetched metadata (consumers read only after next barrier)
        if (pf) { sMeta[cur ^ 1][t] = pm; sR[cur ^ 1][t] = pr; }
        // accumulate phase (all threads): hl = t, 32 channels of head h
        for (int j = 0; j < nb; j++) {
            float p = ps[j][t];
            unsigned long long pp = pk2(p, p);
            const ulonglong2* vp = (const ulonglong2*)(sv[j] + h32);
#pragma unroll
            for (int i = 0; i < 8; i++) {
                ulonglong2 v2 = vp[i];
                fma2(acc[2 * i + 0], pp, v2.x);
                fma2(acc[2 * i + 1], pp, v2.y);
            }
        }
        __syncthreads();
    }
    if (t < 256) *(float2*)&g_psum[(size_t)bs * HL + 2 * t] = make_float2(sum0, sum1);
    float* pa = g_pacc + (size_t)bs * 32 * HL;
#pragma unroll
    for (int k = 0; k < 16; k++) {
        float c0, c1;
        upk2(c0, c1, acc[k]);
        pa[(2 * k + 0) * HL + t] = c0;
        pa[(2 * k + 1) * HL + t] = c1;
    }
}

// grid (NBATCH, 32): block (b, channel i); threads = hl
__global__ void k_reduce() {
    int b = blockIdx.x, i = blockIdx.y, hl = threadIdx.x;
    float tot = 0;
#pragma unroll
    for (int s = 0; s < NSPLIT; s++) tot += g_psum[(size_t)(b * NSPLIT + s) * HL + hl];
    float inv = (tot > 0.f) ? 1.0f / tot : 0.f;
    float o = 0;
#pragma unroll
    for (int s = 0; s < NSPLIT; s++)
        o += g_pacc[(size_t)(b * NSPLIT + s) * 32 * HL + (size_t)i * HL + hl];
    int h = hl >> 6, l = hl & 63;
    g_attv[((size_t)(b * LL + l)) * DD + h * 32 + i] = o * inv;
}

__global__ void k_prefill(const float* __restrict__ lat0) {
    int row = blockIdx.x, t = threadIdx.x;
    g_lat[(size_t)row * DD + t] = lat0[(row & 63) * DD + t];
}

// ---------------- latent self-attention (per (b,h)) ----------------
__global__ void k_selfattn(const float* __restrict__ qkv, float* __restrict__ obuf) {
    int b = blockIdx.x >> 3, h = blockIdx.x & 7;
    __shared__ float qs[64][33], ks[64][33], vs[64][33], ps[64][65];
    int t = threadIdx.x;
    for (int id = t; id < 64 * 32; id += 256) {
        int l = id >> 5, i = id & 31;
        const float* base = qkv + ((size_t)(b * LL + l)) * 768 + h * 32 + i;
        qs[l][i] = base[0];
        ks[l][i] = base[256];
        vs[l][i] = base[512];
    }
    __syncthreads();
    int ql = t >> 2, k0 = (t & 3) * 16;
    for (int kk = 0; kk < 16; kk++) {
        int k = k0 + kk;
        float s = 0;
#pragma unroll
        for (int d = 0; d < 32; d++) s = fmaf(qs[ql][d], ks[k][d], s);
        ps[ql][k] = s * 0.17677669529663687f;
    }
    __syncthreads();
    if (t < 64) {
        float mx = -1e30f;
        for (int k = 0; k < 64; k++) mx = fmaxf(mx, ps[t][k]);
        float sum = 0;
        for (int k = 0; k < 64; k++) { float p = __expf(ps[t][k] - mx); ps[t][k] = p; sum += p; }
        float inv = 1.0f / sum;
        for (int k = 0; k < 64; k++) ps[t][k] *= inv;
    }
    __syncthreads();
    int i = t & 31, l0 = t >> 5;
    for (int j = 0; j < 8; j++) {
        int l = l0 + j * 8;
        float o = 0;
        for (int k = 0; k < 64; k++) o = fmaf(ps[l][k], vs[k][i], o);
        obuf[((size_t)(b * LL + l)) * DD + h * 32 + i] = o;
    }
}

// ---------------- behavior decoder + logits ----------------
__global__ void k_behav(const float* __restrict__ bh_wo, float* __restrict__ out) {
    int b = blockIdx.x, t = threadIdx.x;
    __shared__ float sc[16][65];
    __shared__ float ov[2][256];
    __shared__ float red[8];
    for (int id = t; id < 1024; id += 256) {
        int jh = id >> 6, k = id & 63;
        int j = jh >> 3, h = jh & 7;
        const float* kr = g_kvb + ((size_t)(b * LL + k)) * 512 + h * 32;
        const float* qr = g_qb + j * DD + h * 32;
        float s = 0;
#pragma unroll
        for (int d = 0; d < 32; d++) s = fmaf(qr[d], kr[d], s);
        sc[jh][k] = s * 0.17677669529663687f;
    }
    __syncthreads();
    if (t < 16) {
        float mx = -1e30f;
        for (int k = 0; k < 64; k++) mx = fmaxf(mx, sc[t][k]);
        float sum = 0;
        for (int k = 0; k < 64; k++) { float p = __expf(sc[t][k] - mx); sc[t][k] = p; sum += p; }
        float inv = 1.0f / sum;
        for (int k = 0; k < 64; k++) sc[t][k] *= inv;
    }
    __syncthreads();
    for (int id = t; id < 512; id += 256) {
        int j = id >> 8, c = id & 255, h = c >> 5;
        float o = 0;
        for (int k = 0; k < 64; k++)
            o = fmaf(sc[j * 8 + h][k], g_kvb[((size_t)(b * LL + k)) * 512 + 256 + c], o);
        ov[j][c] = o;
    }
    __syncthreads();
    for (int j = 0; j < 2; j++) {
        float v = ov[j][t] * bh_wo[t];
#pragma unroll
        for (int o = 16; o > 0; o >>= 1) v += __shfl_xor_sync(~0u, v, o);
        if ((t & 31) == 0) red[t >> 5] = v;
        __syncthreads();
        if (t == 0) {
            float s = 0;
            for (int w = 0; w < 8; w++) s += red[w];
            out[b * 2 + j] = s;
        }
        __syncthreads();
    }
}

__global__ void k_logits(const float* __restrict__ sp_w, const float* __restrict__ sp_b,
                         float* __restrict__ out) {
    int b = blockIdx.x, t = threadIdx.x;
    __shared__ float mean[DD];
    float s = 0;
    for (int l = 0; l < LL; l++) s += g_lat[((size_t)(b * LL + l)) * DD + t];
    mean[t] = s * (1.0f / LL);
    __syncthreads();
    if (t < 64) {
        float a = sp_b[t];
        for (int d = 0; d < DD; d++) a = fmaf(mean[d], sp_w[d * 64 + t], a);
        out[32 + b * 64 + t] = a;
    }
}

// ---------------- host driver ----------------
extern "C" void kernel_launch(void* const* d_in, const int* in_sizes, int n_in,
                              void* d_out, int out_size) {
    const float* W[21];
    int wi = 0;
    const int* ids[4] = {nullptr, nullptr, nullptr, nullptr};
    int E = 0;
    for (int i = 0; i < n_in; i++) {
        int s = in_sizes[i];
        if (s <= 2) continue;
        if (!E && s >= 50000 && i + 3 < n_in && in_sizes[i + 1] == s &&
            in_sizes[i + 2] == s && in_sizes[i + 3] == s) {
            for (int j = 0; j < 4; j++) ids[j] = (const int*)d_in[i + j];
            E = s;
            i += 3;
            continue;
        }
        if (wi < 21) W[wi++] = (const float*)d_in[i];
    }
    const float *ne = W[0], *te = W[1], *ve = W[2], *lat0 = W[3], *Wq = W[4], *Wkv = W[5],
                *Wo = W[6], *W1 = W[7], *W2 = W[8], *Wqkv_s = W[9], *Wo_s = W[10],
                *W1_s = W[11], *W2_s = W[12], *bhq = W[13], *bhwq = W[14], *bhwkv = W[15],
                *bhwo = W[16], *lnw = W[17], *lnb = W[18], *spw = W[19], *spb = W[20];
    const int *nid = ids[0], *tbv = ids[1], *vlv = ids[2], *bix = ids[3];
    float* out = (float*)d_out;

    float *p_embcat, *p_Wc, *p_xl, *p_h, *p_lat, *p_qkv, *p_obuf, *p_kvb, *p_qb, *p_attv;
    cudaGetSymbolAddress((void**)&p_embcat, g_embcat);
    cudaGetSymbolAddress((void**)&p_Wc, g_Wc);
    cudaGetSymbolAddress((void**)&p_xl, g_xl);
    cudaGetSymbolAddress((void**)&p_h, g_h);
    cudaGetSymbolAddress((void**)&p_lat, g_lat);
    cudaGetSymbolAddress((void**)&p_qkv, g_qkv);
    cudaGetSymbolAddress((void**)&p_obuf, g_obuf);
    cudaGetSymbolAddress((void**)&p_kvb, g_kvb);
    cudaGetSymbolAddress((void**)&p_qb, g_qb);
    cudaGetSymbolAddress((void**)&p_attv, g_attv);

    int nch = (E + 1023) >> 10;

    // --- precompute tables ---
    k_copy_emb<<<NROWS, 256>>>(ne, te, ve);
    k_rowstats<<<NROWS, 256>>>();
    k_ln<<<64, 256>>>(lat0, p_xl);
    k_q<<<64, 256>>>(Wq);
    k_colsum<<<2, 256>>>(Wkv);
    k_qc<<<1, 512>>>();
    k_buildWc<<<256, 768>>>(Wkv);
    {
        dim3 g(42, 6);
        k_gemm<<<g, 256>>>(p_embcat, p_Wc, nullptr, NROWS, 256, 768, 4);
    }

    // --- event grouping + stats ---
    k_count<<<nch, 256>>>(bix, E);
    k_scan<<<1, 16>>>(nch);
    k_scatter<<<nch, 32>>>(bix, E);
    k_stats<<<(E + 7) / 8, 256>>>(nid, tbv, vlv, E);

    // --- fused cross attention ---
    k_cross<<<NBATCH * NSPLIT, 512>>>(nid, tbv, vlv);
    { dim3 g(NBATCH, 32); k_reduce<<<g, 512>>>(); }

    // --- latent pipeline ---
    k_prefill<<<NBATCH * LL, 256>>>(lat0);
    { dim3 g(16, 4);  k_gemm64<<<g, 256>>>(p_attv, Wo, p_lat, 1024, 256, 256, 2, nullptr, nullptr); }
    k_lnstats<<<128, 256>>>(p_lat, 1024);
    { dim3 g(16, 16); k_gemm64<<<g, 256>>>(p_lat, W1, p_h, 1024, 256, 1024, 8 | 1, nullptr, nullptr); }
    { dim3 g(16, 4);  k_gemm64<<<g, 256>>>(p_h, W2, p_lat, 1024, 1024, 256, 2, nullptr, nullptr); }

    for (int i = 0; i < 2; i++) {
        k_lnstats<<<128, 256>>>(p_lat, 1024);
        { dim3 g(16, 12); k_gemm64<<<g, 256>>>(p_lat, Wqkv_s + (size_t)i * 256 * 768, p_qkv, 1024, 256, 768, 8, nullptr, nullptr); }
        k_selfattn<<<NBATCH * 8, 256>>>(p_qkv, p_obuf);
        { dim3 g(16, 4);  k_gemm64<<<g, 256>>>(p_obuf, Wo_s + (size_t)i * 256 * 256, p_lat, 1024, 256, 256, 2, nullptr, nullptr); }
        k_lnstats<<<128, 256>>>(p_lat, 1024);
        { dim3 g(16, 16); k_gemm64<<<g, 256>>>(p_lat, W1_s + (size_t)i * 256 * 1024, p_h, 1024, 256, 1024, 8 | 1, nullptr, nullptr); }
        { dim3 g(16, 4);  k_gemm64<<<g, 256>>>(p_h, W2_s + (size_t)i * 1024 * 256, p_lat, 1024, 1024, 256, 2, nullptr, nullptr); }
    }

    // --- behavior decoder (affine LN fused into KV GEMM) ---
    k_lnstats<<<128, 256>>>(p_lat, 1024);
    { dim3 g(16, 8); k_gemm64<<<g, 256>>>(p_lat, bhwkv, p_kvb, 1024, 256, 512, 8, lnw, lnb); }
    { dim3 g(1, 4);  k_gemm64<<<g, 256>>>(bhq, bhwq, p_qb, 2, 256, 256, 0, nullptr, nullptr); }
    k_behav<<<NBATCH, 256>>>(bhwo, out);

    // --- spike logits ---
    k_logits<<<NBATCH, 256>>>(spw, spb, out);
}

// round 8
// speedup vs baseline: 1.3060x; 1.0054x over previous
#include <cuda_runtime.h>
#include <cuda_bf16.h>
#include <cstddef>

#define DD 256
#define HH 8
#define LL 64
#define HL 512
#define NEURONS 4096
#define TBINS 1024
#define VBUCK 256
#define NBATCH 16
#define EVSTRIDE 13600
#define MAXE 200704
#define NSPLIT 9
#define NROWS 5376

// ---------------- static device scratch ----------------
__device__ __align__(16) float g_embcat[NROWS * DD];
__device__ float g_rowmean[NROWS];
__device__ float g_rowmsq[NROWS];
__device__ __align__(16) float g_qh[HL * 32];
__device__ __align__(8) float g_colV[256];
__device__ __align__(8) float g_qcK[HL];
__device__ __align__(16) float g_Wc[DD * 768];
__device__ __align__(16) __nv_bfloat16 g_Ts[NROWS * 512];   // bf16 score table
__device__ __align__(16) float g_Tv[NROWS * 256];           // fp32 V table
__device__ float g_me[MAXE];
__device__ float g_re[MAXE];
__device__ int   g_cnt[NBATCH];
__device__ int   g_chunkcnt[256 * NBATCH];
__device__ int   g_chunkbase[256 * NBATCH];
__device__ int   g_evlist[NBATCH * EVSTRIDE];
__device__ __align__(8) float g_psum[NBATCH * NSPLIT * HL];
__device__ float g_pacc[NBATCH * NSPLIT * 32 * HL];
__device__ __align__(16) float g_attv[NBATCH * LL * DD];
__device__ __align__(16) float g_lat [NBATCH * LL * DD];
__device__ __align__(16) float g_h   [NBATCH * LL * 1024];
__device__ __align__(16) float g_qkv [NBATCH * LL * 768];
__device__ __align__(16) float g_obuf[NBATCH * LL * DD];
__device__ __align__(16) float g_kvb [NBATCH * LL * 512];

// ---------------- f32x2 helpers ----------------
__device__ __forceinline__ void fma2(unsigned long long& d, unsigned long long a, unsigned long long b) {
    asm("fma.rn.f32x2 %0, %1, %2, %0;" : "+l"(d) : "l"(a), "l"(b));
}
__device__ __forceinline__ unsigned long long pk2(float x, float y) {
    unsigned long long r;
    asm("mov.b64 %0, {%1, %2};" : "=l"(r) : "f"(x), "f"(y));
    return r;
}
__device__ __forceinline__ void upk2(float& x, float& y, unsigned long long r) {
    asm("mov.b64 {%0, %1}, %2;" : "=f"(x), "=f"(y) : "l"(r));
}

__device__ __forceinline__ float gelu_f(float x) {
    float x3 = x * x * x;
    float u = 0.7978845608028654f * (x + 0.044715f * x3);
    return 0.5f * x * (1.0f + tanhf(u));
}

// ---------------- prep: copy embeddings + row stats (fused) ----------------
__global__ void k_prep0(const float* __restrict__ ne, const float* __restrict__ te,
                        const float* __restrict__ ve) {
    __shared__ float red[16];
    int r = blockIdx.x, t = threadIdx.x;
    float x;
    if (r < NEURONS)                x = ne[(size_t)r * DD + t];
    else if (r < NEURONS + TBINS)   x = te[(size_t)(r - NEURONS) * DD + t];
    else                            x = ve[(size_t)(r - NEURONS - TBINS) * DD + t];
    g_embcat[(size_t)r * DD + t] = x;
    float s = x, q = x * x;
#pragma unroll
    for (int o = 16; o > 0; o >>= 1) { s += __shfl_xor_sync(~0u, s, o); q += __shfl_xor_sync(~0u, q, o); }
    if ((t & 31) == 0) { red[t >> 5] = s; red[8 + (t >> 5)] = q; }
    __syncthreads();
    if (t == 0) {
        float ss = 0, qq = 0;
        for (int i = 0; i < 8; i++) { ss += red[i]; qq += red[8 + i]; }
        g_rowmean[r] = ss * (1.0f / DD);
        g_rowmsq[r]  = qq * (1.0f / DD);
    }
}

// ---------------- prep: LN(lat_init) + q projection (fused) ----------------
// q~[hl][i] = (ln(lat_init)[l] @ Wq_c)[h*32+i] * 32^-0.5,  hl = h*64+l
__global__ void k_prep1(const float* __restrict__ lat0, const float* __restrict__ Wq) {
    __shared__ float red[16];
    __shared__ float xr[DD];
    int l = blockIdx.x, t = threadIdx.x;
    float x = lat0[(size_t)l * DD + t];
    float s = x, q = x * x;
#pragma unroll
    for (int o = 16; o > 0; o >>= 1) { s += __shfl_xor_sync(~0u, s, o); q += __shfl_xor_sync(~0u, q, o); }
    if ((t & 31) == 0) { red[t >> 5] = s; red[8 + (t >> 5)] = q; }
    __syncthreads();
    if (t == 0) {
        float ss = 0, qq = 0;
        for (int i = 0; i < 8; i++) { ss += red[i]; qq += red[8 + i]; }
        red[0] = ss; red[8] = qq;
    }
    __syncthreads();
    float mean = red[0] * (1.0f / DD);
    float var  = red[8] * (1.0f / DD) - mean * mean;
    float rstd = rsqrtf(var + 1e-5f);
    xr[t] = (x - mean) * rstd;
    __syncthreads();
    float a0 = 0, a1 = 0, a2 = 0, a3 = 0;
#pragma unroll 4
    for (int d = 0; d < DD; d += 4) {
        a0 = fmaf(xr[d + 0], Wq[(d + 0) * DD + t], a0);
        a1 = fmaf(xr[d + 1], Wq[(d + 1) * DD + t], a1);
        a2 = fmaf(xr[d + 2], Wq[(d + 2) * DD + t], a2);
        a3 = fmaf(xr[d + 3], Wq[(d + 3) * DD + t], a3);
    }
    float a = (a0 + a1) + (a2 + a3);
    int h = t >> 5, i = t & 31;
    g_qh[((h << 6) + l) * 32 + i] = a * 0.17677669529663687f;
}

// Wc[:, :512] = A (score projection folded with q),  Wc[:, 512:768] = Wkv V-part
__global__ void k_buildWc(const float* __restrict__ Wkv) {
    __shared__ float wr[256];
    int d = blockIdx.x, c = threadIdx.x;
    if (c < 256) wr[c] = Wkv[(size_t)d * 512 + c];
    __syncthreads();
    float out;
    if (c < 512) {
        int h = c >> 6;
        float a = 0;
#pragma unroll
        for (int i = 0; i < 32; i++) a = fmaf(wr[h * 32 + i], g_qh[c * 32 + i], a);
        out = a;
    } else {
        out = Wkv[(size_t)d * 512 + 256 + (c - 512)];
    }
    g_Wc[(size_t)d * 768 + c] = out;
}

// qcK[c] = sum_d Wc[d,c] (c<512); colV[c-512] = sum_d Wc[d,c] (c>=512)
__global__ void k_colred() {
    int j = blockIdx.x * 256 + threadIdx.x;
    float s = 0;
    for (int d = 0; d < DD; d++) s += g_Wc[(size_t)d * 768 + j];
    if (j < 512) g_qcK[j] = s;
    else         g_colV[j - 512] = s;
}

// ---------------- fp32 GEMM, 128x128 tile, 8x8/thread, f32x2 FMA ----------------
// flags: 4 = split-store (bf16 g_Ts cols<512, fp32 g_Tv cols>=512)
__global__ void __launch_bounds__(256) k_gemm(const float* __restrict__ A, const float* __restrict__ W,
                                              float* __restrict__ C, int R, int K, int N, int flags) {
    __shared__ float As[16][132];
    __shared__ float Ws[16][132];
    int t = threadIdx.x;
    int rbase = blockIdx.x * 128, nbase = blockIdx.y * 128;
    int tr = t >> 4, tc = t & 15;
    unsigned long long acc2[8][4];
#pragma unroll
    for (int x = 0; x < 8; x++)
#pragma unroll
        for (int y = 0; y < 4; y++) acc2[x][y] = 0ull;

    for (int k0 = 0; k0 < K; k0 += 16) {
#pragma unroll
        for (int j = 0; j < 2; j++) {
            int q = t * 2 + j;
            int m = q >> 2, k4 = (q & 3) * 4;
            int r = rbase + m;
            float4 av = make_float4(0.f, 0.f, 0.f, 0.f);
            if (r < R) av = *(const float4*)(A + (size_t)r * K + k0 + k4);
            As[k4 + 0][m] = av.x; As[k4 + 1][m] = av.y;
            As[k4 + 2][m] = av.z; As[k4 + 3][m] = av.w;
            int n4 = (q & 31) * 4, kw = q >> 5;
            float4 wv = *(const float4*)(W + (size_t)(k0 + kw) * N + nbase + n4);
            *(float4*)&Ws[kw][n4] = wv;
        }
        __syncthreads();
#pragma unroll
        for (int kk = 0; kk < 16; kk++) {
            float4 aA = *(const float4*)&As[kk][tr * 8];
            float4 aB = *(const float4*)&As[kk][tr * 8 + 4];
            ulonglong2 w0 = *(const ulonglong2*)&Ws[kk][tc * 8];
            ulonglong2 w1 = *(const ulonglong2*)&Ws[kk][tc * 8 + 4];
            float a[8] = {aA.x, aA.y, aA.z, aA.w, aB.x, aB.y, aB.z, aB.w};
#pragma unroll
            for (int x = 0; x < 8; x++) {
                unsigned long long aa = pk2(a[x], a[x]);
                fma2(acc2[x][0], aa, w0.x);
                fma2(acc2[x][1], aa, w0.y);
                fma2(acc2[x][2], aa, w1.x);
                fma2(acc2[x][3], aa, w1.y);
            }
        }
        __syncthreads();
    }
#pragma unroll
    for (int x = 0; x < 8; x++) {
        int r = rbase + tr * 8 + x;
        if (r >= R) break;
        float v[8];
#pragma unroll
        for (int y = 0; y < 4; y++) upk2(v[2 * y], v[2 * y + 1], acc2[x][y]);
        if (flags & 4) {
#pragma unroll
            for (int y = 0; y < 8; y++) {
                int cc = nbase + tc * 8 + y;
                if (cc < 512) g_Ts[(size_t)r * 512 + cc] = __float2bfloat16(v[y]);
                else          g_Tv[(size_t)r * 256 + cc - 512] = v[y];
            }
        } else {
            float* crow = C + (size_t)r * N + nbase + tc * 8;
#pragma unroll
            for (int y = 0; y < 8; y++) crow[y] = v[y];
        }
    }
}

// ---------------- fp32 GEMM, 64x64 tile, 4x4/thread, f32x2 FMA ----------------
// flags: 1 = gelu, 2 = accumulate, 8 = LN on A rows computed in-kernel (K must be 256;
//        optional affine lw/lb), 16 = C = lw[(r&63)*DD + col] + acc (lat0 bias)
__global__ void __launch_bounds__(256) k_gemm64(const float* __restrict__ A, const float* __restrict__ W,
                                                float* __restrict__ C, int R, int K, int N, int flags,
                                                const float* __restrict__ lw, const float* __restrict__ lb) {
    __shared__ float As[16][68];
    __shared__ float Ws[16][68];
    __shared__ float s_lnm[64], s_lnr[64];
    int t = threadIdx.x;
    int rbase = blockIdx.x * 64, nbase = blockIdx.y * 64;
    int tr = t >> 4, tc = t & 15;

    if (flags & 8) {
        // per-row LN stats for the 64 A rows of this block (K == 256)
        int row = t >> 2, part = t & 3;
        const float4* ar = (const float4*)(A + (size_t)(rbase + row) * 256) + part * 16;
        float s = 0, q = 0;
#pragma unroll
        for (int i = 0; i < 16; i++) {
            float4 v = ar[i];
            s += v.x + v.y + v.z + v.w;
            q = fmaf(v.x, v.x, fmaf(v.y, v.y, fmaf(v.z, v.z, fmaf(v.w, v.w, q))));
        }
        s += __shfl_xor_sync(~0u, s, 1); q += __shfl_xor_sync(~0u, q, 1);
        s += __shfl_xor_sync(~0u, s, 2); q += __shfl_xor_sync(~0u, q, 2);
        if (part == 0) {
            float mean = s * (1.0f / 256.0f);
            float var = q * (1.0f / 256.0f) - mean * mean;
            s_lnm[row] = mean;
            s_lnr[row] = rsqrtf(var + 1e-5f);
        }
        __syncthreads();
    }

    unsigned long long acc2[4][2];
#pragma unroll
    for (int x = 0; x < 4; x++) { acc2[x][0] = 0ull; acc2[x][1] = 0ull; }

    int ma = t >> 2, k4 = (t & 3) * 4;       // A: 64 rows x 16k
    int kw = t >> 4, n4 = (t & 15) * 4;      // W: 16k x 64n
    int arow = rbase + ma;
    float lm = 0.f, lr = 1.f;
    if (flags & 8) { lm = s_lnm[ma]; lr = s_lnr[ma]; }

    for (int k0 = 0; k0 < K; k0 += 16) {
        float4 av = make_float4(0.f, 0.f, 0.f, 0.f);
        if (arow < R) av = *(const float4*)(A + (size_t)arow * K + k0 + k4);
        if (flags & 8) {
            av.x = (av.x - lm) * lr; av.y = (av.y - lm) * lr;
            av.z = (av.z - lm) * lr; av.w = (av.w - lm) * lr;
            if (lw) {
                float4 w4 = *(const float4*)(lw + k0 + k4);
                float4 b4 = *(const float4*)(lb + k0 + k4);
                av.x = fmaf(av.x, w4.x, b4.x); av.y = fmaf(av.y, w4.y, b4.y);
                av.z = fmaf(av.z, w4.z, b4.z); av.w = fmaf(av.w, w4.w, b4.w);
            }
        }
        As[k4 + 0][ma] = av.x; As[k4 + 1][ma] = av.y;
        As[k4 + 2][ma] = av.z; As[k4 + 3][ma] = av.w;
        float4 wv = *(const float4*)(W + (size_t)(k0 + kw) * N + nbase + n4);
        *(float4*)&Ws[kw][n4] = wv;
        __syncthreads();
#pragma unroll
        for (int kk = 0; kk < 16; kk++) {
            float4 a4 = *(const float4*)&As[kk][tr * 4];
            ulonglong2 w2 = *(const ulonglong2*)&Ws[kk][tc * 4];
            float a[4] = {a4.x, a4.y, a4.z, a4.w};
#pragma unroll
            for (int x = 0; x < 4; x++) {
                unsigned long long aa = pk2(a[x], a[x]);
                fma2(acc2[x][0], aa, w2.x);
                fma2(acc2[x][1], aa, w2.y);
            }
        }
        __syncthreads();
    }
#pragma unroll
    for (int x = 0; x < 4; x++) {
        int r = rbase + tr * 4 + x;
        if (r >= R) break;
        float v[4];
        upk2(v[0], v[1], acc2[x][0]);
        upk2(v[2], v[3], acc2[x][1]);
        float* crow = C + (size_t)r * N + nbase + tc * 4;
#pragma unroll
        for (int y = 0; y < 4; y++) {
            float vv = v[y];
            if (flags & 1) vv = gelu_f(vv);
            if (flags & 16)      crow[y] = lw[(size_t)(r & 63) * DD + nbase + tc * 4 + y] + vv;
            else if (flags & 2)  crow[y] += vv;
            else                 crow[y] = vv;
        }
    }
}

// ---------------- deterministic event grouping (counting sort) ----------------
__global__ void k_count(const int* __restrict__ bix, int E) {
    __shared__ int sc[NBATCH];
    int c = blockIdx.x;
    if (threadIdx.x < NBATCH) sc[threadIdx.x] = 0;
    __syncthreads();
    int base = c << 10;
    for (int i = threadIdx.x; i < 1024; i += blockDim.x) {
        int e = base + i;
        if (e < E) atomicAdd(&sc[bix[e]], 1);
    }
    __syncthreads();
    if (threadIdx.x < NBATCH) g_chunkcnt[c * NBATCH + threadIdx.x] = sc[threadIdx.x];
}

__global__ void k_scan(int nch) {
    int b = threadIdx.x;
    if (b < NBATCH) {
        int run = 0;
        for (int c = 0; c < nch; c++) {
            int v = g_chunkcnt[c * NBATCH + b];
            g_chunkbase[c * NBATCH + b] = run;
            run += v;
        }
        g_cnt[b] = run;
    }
}

__global__ void k_scatter(const int* __restrict__ bix, int E) {
    __shared__ int loc[48];
    int c = blockIdx.x, lane = threadIdx.x;
    if (lane < NBATCH) loc[lane] = g_chunkbase[c * NBATCH + lane];
    loc[16 + lane] = 0;
    __syncwarp();
    int base = c << 10;
    for (int i = 0; i < 32; i++) {
        int e = base + i * 32 + lane;
        bool valid = e < E;
        int b_ = 0;
        if (valid) b_ = bix[e];
        int bb = valid ? b_ : 16 + lane;
        unsigned mm = __match_any_sync(0xffffffffu, bb);
        int rank = __popc(mm & ((1u << lane) - 1u));
        int leader = __ffs(mm) - 1;
        int start = 0;
        if (lane == leader) { start = loc[bb]; loc[bb] = start + __popc(mm); }
        start = __shfl_sync(0xffffffffu, start, leader);
        if (valid) g_evlist[b_ * EVSTRIDE + start + rank] = e;
        __syncwarp();
    }
}

// ---------------- per-event LN stats ----------------
__global__ void k_stats(const int* __restrict__ nid, const int* __restrict__ tb,
                        const int* __restrict__ vl, int E) {
    int e = blockIdx.x * 8 + (threadIdx.x >> 5);
    int lane = threadIdx.x & 31;
    if (e >= E) return;
    int n = nid[e], t = tb[e], v = vl[e];
    const float4* rn = (const float4*)(g_embcat + (size_t)n * DD);
    const float4* rt = (const float4*)(g_embcat + (size_t)(NEURONS + t) * DD);
    const float4* rv = (const float4*)(g_embcat + (size_t)(NEURONS + TBINS + v) * DD);
    float dnt = 0, dnv = 0, dtv = 0;
#pragma unroll
    for (int d = 0; d < 2; d++) {
        int i = lane + d * 32;
        float4 a = rn[i], b = rt[i], c = rv[i];
        dnt = fmaf(a.x, b.x, fmaf(a.y, b.y, fmaf(a.z, b.z, fmaf(a.w, b.w, dnt))));
        dnv = fmaf(a.x, c.x, fmaf(a.y, c.y, fmaf(a.z, c.z, fmaf(a.w, c.w, dnv))));
        dtv = fmaf(b.x, c.x, fmaf(b.y, c.y, fmaf(b.z, c.z, fmaf(b.w, c.w, dtv))));
    }
#pragma unroll
    for (int o = 16; o > 0; o >>= 1) {
        dnt += __shfl_xor_sync(~0u, dnt, o);
        dnv += __shfl_xor_sync(~0u, dnv, o);
        dtv += __shfl_xor_sync(~0u, dtv, o);
    }
    if (lane == 0) {
        float m = g_rowmean[n] + g_rowmean[NEURONS + t] + g_rowmean[NEURONS + TBINS + v];
        float msq = g_rowmsq[n] + g_rowmsq[NEURONS + t] + g_rowmsq[NEURONS + TBINS + v]
                  + (dnt + dnv + dtv) * (2.0f / DD);
        float var = msq - m * m;
        g_me[e] = m;
        g_re[e] = rsqrtf(var + 1e-5f);
    }
}

// ---------------- fused ragged cross-attention ----------------
__global__ void __launch_bounds__(512, 1) k_cross(const int* __restrict__ nid,
                                                  const int* __restrict__ tb,
                                                  const int* __restrict__ vl) {
    int bs = blockIdx.x;
    int b = bs / NSPLIT, sp = bs - b * NSPLIT;
    int t = threadIdx.x;
    int cnt = g_cnt[b];
    if (cnt > EVSTRIDE) cnt = EVSTRIDE;
    int e0 = (int)((long long)cnt * sp / NSPLIT);
    int e1 = (int)((long long)cnt * (sp + 1) / NSPLIT);

    __shared__ float sv[8][256];
    __shared__ float ps[8][512];
    __shared__ int4  sMeta[2][8];
    __shared__ float sR[2][8];

    const __nv_bfloat162* __restrict__ Ts2 = (const __nv_bfloat162*)g_Ts;
    const float2* __restrict__ Tv2 = (const float2*)g_Tv;

    float2 qc2 = make_float2(0.f, 0.f);
    float2 cv2 = make_float2(0.f, 0.f);
    if (t < 256) qc2 = *(const float2*)&g_qcK[2 * t];
    else if (t < 384) cv2 = *(const float2*)&g_colV[2 * (t - 256)];

    unsigned long long acc[16];
#pragma unroll
    for (int i = 0; i < 16; i++) acc[i] = 0ull;
    float sum0 = 0.f, sum1 = 0.f;
    int h32 = (t >> 6) << 5;
    const int* evl = g_evlist + b * EVSTRIDE;

    if (t < 8 && e0 + t < e1) {
        int e = evl[e0 + t];
        int n_ = nid[e], tt_ = tb[e], vv_ = vl[e];
        float r_ = g_re[e], m_ = g_me[e];
        sMeta[0][t] = make_int4(n_, NEURONS + tt_, NEURONS + TBINS + vv_, __float_as_int(-r_ * m_));
        sR[0][t] = r_;
    }
    __syncthreads();

    int cur = 0;
    for (int base = e0; base < e1; base += 8, cur ^= 1) {
        int nb = min(8, e1 - base);
        bool pf = (t < 8) && (base + 8 + t < e1);
        int4 pm; float pr = 0.f;
        if (pf) {
            int e = evl[base + 8 + t];
            int n_ = nid[e], tt_ = tb[e], vv_ = vl[e];
            float r_ = g_re[e], m_ = g_me[e];
            pm = make_int4(n_, NEURONS + tt_, NEURONS + TBINS + vv_, __float_as_int(-r_ * m_));
            pr = r_;
        }
        if (t < 256) {
            for (int j = 0; j < nb; j++) {
                int4 mm = sMeta[cur][j];
                float r = sR[cur][j];
                float rm = __int_as_float(mm.w);
                float2 fa = __bfloat1622float2(Ts2[(size_t)mm.x * 256 + t]);
                float2 fb = __bfloat1622float2(Ts2[(size_t)mm.y * 256 + t]);
                float2 fc = __bfloat1622float2(Ts2[(size_t)mm.z * 256 + t]);
                float s0 = fmaf(r, fa.x + fb.x + fc.x, rm * qc2.x);
                float s1 = fmaf(r, fa.y + fb.y + fc.y, rm * qc2.y);
                float p0 = __expf(s0), p1 = __expf(s1);
                sum0 += p0; sum1 += p1;
                *(float2*)&ps[j][2 * t] = make_float2(p0, p1);
            }
        } else if (t < 384) {
            int u = t - 256;
            for (int j = 0; j < nb; j++) {
                int4 mm = sMeta[cur][j];
                float r = sR[cur][j];
                float rm = __int_as_float(mm.w);
                float2 va = Tv2[(size_t)mm.x * 128 + u];
                float2 vb = Tv2[(size_t)mm.y * 128 + u];
                float2 vc = Tv2[(size_t)mm.z * 128 + u];
                float2 o;
                o.x = fmaf(r, va.x + vb.x + vc.x, rm * cv2.x);
                o.y = fmaf(r, va.y + vb.y + vc.y, rm * cv2.y);
                *(float2*)&sv[j][2 * u] = o;
            }
        }
        __syncthreads();
        if (pf) { sMeta[cur ^ 1][t] = pm; sR[cur ^ 1][t] = pr; }
        for (int j = 0; j < nb; j++) {
            float p = ps[j][t];
            unsigned long long pp = pk2(p, p);
            const ulonglong2* vp = (const ulonglong2*)(sv[j] + h32);
#pragma unroll
            for (int i = 0; i < 8; i++) {
                ulonglong2 v2 = vp[i];
                fma2(acc[2 * i + 0], pp, v2.x);
                fma2(acc[2 * i + 1], pp, v2.y);
            }
        }
        __syncthreads();
    }
    if (t < 256) *(float2*)&g_psum[(size_t)bs * HL + 2 * t] = make_float2(sum0, sum1);
    float* pa = g_pacc + (size_t)bs * 32 * HL;
#pragma unroll
    for (int k = 0; k < 16; k++) {
        float c0, c1;
        upk2(c0, c1, acc[k]);
        pa[(2 * k + 0) * HL + t] = c0;
        pa[(2 * k + 1) * HL + t] = c1;
    }
}

// grid (NBATCH, 32): block (b, channel i); threads = hl
__global__ void k_reduce() {
    int b = blockIdx.x, i = blockIdx.y, hl = threadIdx.x;
    float tot = 0;
#pragma unroll
    for (int s = 0; s < NSPLIT; s++) tot += g_psum[(size_t)(b * NSPLIT + s) * HL + hl];
    float inv = (tot > 0.f) ? 1.0f / tot : 0.f;
    float o = 0;
#pragma unroll
    for (int s = 0; s < NSPLIT; s++)
        o += g_pacc[(size_t)(b * NSPLIT + s) * 32 * HL + (size_t)i * HL + hl];
    int h = hl >> 6, l = hl & 63;
    g_attv[((size_t)(b * LL + l)) * DD + h * 32 + i] = o * inv;
}

// ---------------- latent self-attention (per (b,h)) ----------------
__global__ void k_selfattn(const float* __restrict__ qkv, float* __restrict__ obuf) {
    int b = blockIdx.x >> 3, h = blockIdx.x & 7;
    __shared__ float qs[64][33], ks[64][33], vs[64][33], ps[64][65];
    int t = threadIdx.x;
    for (int id = t; id < 64 * 32; id += 256) {
        int l = id >> 5, i = id & 31;
        const float* base = qkv + ((size_t)(b * LL + l)) * 768 + h * 32 + i;
        qs[l][i] = base[0];
        ks[l][i] = base[256];
        vs[l][i] = base[512];
    }
    __syncthreads();
    int ql = t >> 2, k0 = (t & 3) * 16;
    for (int kk = 0; kk < 16; kk++) {
        int k = k0 + kk;
        float s = 0;
#pragma unroll
        for (int d = 0; d < 32; d++) s = fmaf(qs[ql][d], ks[k][d], s);
        ps[ql][k] = s * 0.17677669529663687f;
    }
    __syncthreads();
    if (t < 64) {
        float mx = -1e30f;
        for (int k = 0; k < 64; k++) mx = fmaxf(mx, ps[t][k]);
        float sum = 0;
        for (int k = 0; k < 64; k++) { float p = __expf(ps[t][k] - mx); ps[t][k] = p; sum += p; }
        float inv = 1.0f / sum;
        for (int k = 0; k < 64; k++) ps[t][k] *= inv;
    }
    __syncthreads();
    int i = t & 31, l0 = t >> 5;
    for (int j = 0; j < 8; j++) {
        int l = l0 + j * 8;
        float o = 0;
        for (int k = 0; k < 64; k++) o = fmaf(ps[l][k], vs[k][i], o);
        obuf[((size_t)(b * LL + l)) * DD + h * 32 + i] = o;
    }
}

// ---------------- behavior decoder + spike logits (fully fused) ----------------
__global__ void k_behav(const float* __restrict__ bhq, const float* __restrict__ bhwq,
                        const float* __restrict__ bh_wo,
                        const float* __restrict__ sp_w, const float* __restrict__ sp_b,
                        float* __restrict__ out) {
    int b = blockIdx.x, t = threadIdx.x;
    __shared__ float bq[512];
    __shared__ float qs2[2][256];
    __shared__ float sc[16][65];
    __shared__ float ov[2][256];
    __shared__ float red[8];
    __shared__ float mean[DD];
    bq[t] = bhq[t];
    bq[256 + t] = bhq[256 + t];
    float s = 0;
    for (int l = 0; l < LL; l++) s += g_lat[((size_t)(b * LL + l)) * DD + t];
    mean[t] = s * (1.0f / LL);
    __syncthreads();
#pragma unroll
    for (int j = 0; j < 2; j++) {
        float a = 0;
        for (int d = 0; d < DD; d++) a = fmaf(bq[j * DD + d], bhwq[d * DD + t], a);
        qs2[j][t] = a;
    }
    __syncthreads();
    for (int id = t; id < 1024; id += 256) {
        int jh = id >> 6, k = id & 63;
        int j = jh >> 3, h = jh & 7;
        const float* kr = g_kvb + ((size_t)(b * LL + k)) * 512 + h * 32;
        const float* qr = &qs2[j][h * 32];
        float sa = 0;
#pragma unroll
        for (int d = 0; d < 32; d++) sa = fmaf(qr[d], kr[d], sa);
        sc[jh][k] = sa * 0.17677669529663687f;
    }
    __syncthreads();
    if (t < 16) {
        float mx = -1e30f;
        for (int k = 0; k < 64; k++) mx = fmaxf(mx, sc[t][k]);
        float sum = 0;
        for (int k = 0; k < 64; k++) { float p = __expf(sc[t][k] - mx); sc[t][k] = p; sum += p; }
        float inv = 1.0f / sum;
        for (int k = 0; k < 64; k++) sc[t][k] *= inv;
    }
    __syncthreads();
    for (int id = t; id < 512; id += 256) {
        int j = id >> 8, c = id & 255, h = c >> 5;
        float o = 0;
        for (int k = 0; k < 64; k++)
            o = fmaf(sc[j * 8 + h][k], g_kvb[((size_t)(b * LL + k)) * 512 + 256 + c], o);
        ov[j][c] = o;
    }
    __syncthreads();
    for (int j = 0; j < 2; j++) {
        float v = ov[j][t] * bh_wo[t];
#pragma unroll
        for (int o = 16; o > 0; o >>= 1) v += __shfl_xor_sync(~0u, v, o);
        if ((t & 31) == 0) red[t >> 5] = v;
        __syncthreads();
        if (t == 0) {
            float ssum = 0;
            for (int w = 0; w < 8; w++) ssum += red[w];
            out[b * 2 + j] = ssum;
        }
        __syncthreads();
    }
    if (t < 64) {
        float a = sp_b[t];
        for (int d = 0; d < DD; d++) a = fmaf(mean[d], sp_w[d * 64 + t], a);
        out[32 + b * 64 + t] = a;
    }
}

// ---------------- host driver ----------------
extern "C" void kernel_launch(void* const* d_in, const int* in_sizes, int n_in,
                              void* d_out, int out_size) {
    const float* W[21];
    int wi = 0;
    const int* ids[4] = {nullptr, nullptr, nullptr, nullptr};
    int E = 0;
    for (int i = 0; i < n_in; i++) {
        int s = in_sizes[i];
        if (s <= 2) continue;
        if (!E && s >= 50000 && i + 3 < n_in && in_sizes[i + 1] == s &&
            in_sizes[i + 2] == s && in_sizes[i + 3] == s) {
            for (int j = 0; j < 4; j++) ids[j] = (const int*)d_in[i + j];
            E = s;
            i += 3;
            continue;
        }
        if (wi < 21) W[wi++] = (const float*)d_in[i];
    }
    const float *ne = W[0], *te = W[1], *ve = W[2], *lat0 = W[3], *Wq = W[4], *Wkv = W[5],
                *Wo = W[6], *W1 = W[7], *W2 = W[8], *Wqkv_s = W[9], *Wo_s = W[10],
                *W1_s = W[11], *W2_s = W[12], *bhq = W[13], *bhwq = W[14], *bhwkv = W[15],
                *bhwo = W[16], *lnw = W[17], *lnb = W[18], *spw = W[19], *spb = W[20];
    const int *nid = ids[0], *tbv = ids[1], *vlv = ids[2], *bix = ids[3];
    float* out = (float*)d_out;

    float *p_embcat, *p_Wc, *p_h, *p_lat, *p_qkv, *p_obuf, *p_kvb, *p_attv;
    cudaGetSymbolAddress((void**)&p_embcat, g_embcat);
    cudaGetSymbolAddress((void**)&p_Wc, g_Wc);
    cudaGetSymbolAddress((void**)&p_h, g_h);
    cudaGetSymbolAddress((void**)&p_lat, g_lat);
    cudaGetSymbolAddress((void**)&p_qkv, g_qkv);
    cudaGetSymbolAddress((void**)&p_obuf, g_obuf);
    cudaGetSymbolAddress((void**)&p_kvb, g_kvb);
    cudaGetSymbolAddress((void**)&p_attv, g_attv);

    int nch = (E + 1023) >> 10;

    // --- precompute tables (T-GEMM placed at launch index 3 for ncu capture) ---
    k_prep0<<<NROWS, 256>>>(ne, te, ve);
    k_prep1<<<64, 256>>>(lat0, Wq);
    k_buildWc<<<256, 768>>>(Wkv);
    {
        dim3 g(42, 6);
        k_gemm<<<g, 256>>>(p_embcat, p_Wc, nullptr, NROWS, 256, 768, 4);
    }
    k_colred<<<3, 256>>>();

    // --- event grouping + stats ---
    k_count<<<nch, 256>>>(bix, E);
    k_scan<<<1, 16>>>(nch);
    k_scatter<<<nch, 32>>>(bix, E);
    k_stats<<<(E + 7) / 8, 256>>>(nid, tbv, vlv, E);

    // --- fused cross attention ---
    k_cross<<<NBATCH * NSPLIT, 512>>>(nid, tbv, vlv);
    { dim3 g(NBATCH, 32); k_reduce<<<g, 512>>>(); }

    // --- latent pipeline (LN fused into GEMMs; lat0 bias fused into Wo GEMM) ---
    { dim3 g(16, 4);  k_gemm64<<<g, 256>>>(p_attv, Wo, p_lat, 1024, 256, 256, 16, lat0, nullptr); }
    { dim3 g(16, 16); k_gemm64<<<g, 256>>>(p_lat, W1, p_h, 1024, 256, 1024, 8 | 1, nullptr, nullptr); }
    { dim3 g(16, 4);  k_gemm64<<<g, 256>>>(p_h, W2, p_lat, 1024, 1024, 256, 2, nullptr, nullptr); }

    for (int i = 0; i < 2; i++) {
        { dim3 g(16, 12); k_gemm64<<<g, 256>>>(p_lat, Wqkv_s + (size_t)i * 256 * 768, p_qkv, 1024, 256, 768, 8, nullptr, nullptr); }
        k_selfattn<<<NBATCH * 8, 256>>>(p_qkv, p_obuf);
        { dim3 g(16, 4);  k_gemm64<<<g, 256>>>(p_obuf, Wo_s + (size_t)i * 256 * 256, p_lat, 1024, 256, 256, 2, nullptr, nullptr); }
        { dim3 g(16, 16); k_gemm64<<<g, 256>>>(p_lat, W1_s + (size_t)i * 256 * 1024, p_h, 1024, 256, 1024, 8 | 1, nullptr, nullptr); }
        { dim3 g(16, 4);  k_gemm64<<<g, 256>>>(p_h, W2_s + (size_t)i * 1024 * 256, p_lat, 1024, 1024, 256, 2, nullptr, nullptr); }
    }

    // --- behavior decoder + logits (affine LN fused into KV GEMM; qb + logits fused in) ---
    { dim3 g(16, 8); k_gemm64<<<g, 256>>>(p_lat, bhwkv, p_kvb, 1024, 256, 512, 8, lnw, lnb); }
    k_behav<<<NBATCH, 256>>>(bhq, bhwq, bhwo, spw, spb, out);
}